// round 1
// baseline (speedup 1.0000x reference)
#include <cuda_runtime.h>

#define SEQL 4096
#define DMODEL 1024
#define NH 16
#define DKH 64

// Scratch (allocation-free rule: static device globals)
static __device__ float g_Qh[SEQL * DMODEL];
static __device__ float g_Kh[SEQL * DMODEL];
static __device__ float g_Vh[SEQL * DMODEL];
static __device__ float g_Hd[SEQL * DMODEL];

// ---------------------------------------------------------------------------
// FP32 SGEMM: C[M=4096, N=1024] = A[4096,1024] @ B[1024,1024]
// blockedB=1: B is W_[h][d][k] head-blocked (element (d, j) at h*65536 + d*64 + k,
//             h=j>>6, k=j&63). blockedB=0: plain row-major [1024,1024].
// 128x128 tile, BK=8, 256 threads, 8x8 micro-tile, float4 everywhere.
// ---------------------------------------------------------------------------
__global__ __launch_bounds__(256, 2) void sgemm_kernel(
    const float* __restrict__ A, const float* __restrict__ B,
    float* __restrict__ C, int blockedB)
{
    __shared__ float As[8 * 128];   // As[k][m] (transposed)
    __shared__ float Bs[8 * 128];   // Bs[k][n]
    const int tid = threadIdx.x;
    const int tx = tid & 15;
    const int ty = tid >> 4;
    const int m0 = blockIdx.y * 128;
    const int n0 = blockIdx.x * 128;

    const int ar = tid >> 1;          // 0..127 row within A tile
    const int ac = (tid & 1) * 4;     // 0 or 4 (k offset)
    const int bk = tid >> 5;          // 0..7   k row within B tile
    const int bn = (tid & 31) * 4;    // 0..124 col within B tile
    const int bcol = n0 + bn;

    float acc[8][8];
#pragma unroll
    for (int i = 0; i < 8; i++)
#pragma unroll
        for (int j = 0; j < 8; j++) acc[i][j] = 0.f;

    for (int k0 = 0; k0 < DMODEL; k0 += 8) {
        float4 av = *(const float4*)(A + (m0 + ar) * DMODEL + k0 + ac);
        const float* bp = blockedB
            ? (B + (bcol >> 6) * (DMODEL * DKH) + (k0 + bk) * DKH + (bcol & 63))
            : (B + (k0 + bk) * DMODEL + bcol);
        float4 bv = *(const float4*)bp;

        As[(ac + 0) * 128 + ar] = av.x;
        As[(ac + 1) * 128 + ar] = av.y;
        As[(ac + 2) * 128 + ar] = av.z;
        As[(ac + 3) * 128 + ar] = av.w;
        *(float4*)(Bs + bk * 128 + bn) = bv;
        __syncthreads();

#pragma unroll
        for (int kk = 0; kk < 8; kk++) {
            float a[8], b[8];
            *(float4*)&a[0] = *(const float4*)(As + kk * 128 + ty * 8);
            *(float4*)&a[4] = *(const float4*)(As + kk * 128 + ty * 8 + 4);
            *(float4*)&b[0] = *(const float4*)(Bs + kk * 128 + tx * 8);
            *(float4*)&b[4] = *(const float4*)(Bs + kk * 128 + tx * 8 + 4);
#pragma unroll
            for (int i = 0; i < 8; i++)
#pragma unroll
                for (int j = 0; j < 8; j++)
                    acc[i][j] = fmaf(a[i], b[j], acc[i][j]);
        }
        __syncthreads();
    }

#pragma unroll
    for (int i = 0; i < 8; i++) {
        float* cp = C + (m0 + ty * 8 + i) * DMODEL + n0 + tx * 8;
        *(float4*)cp       = make_float4(acc[i][0], acc[i][1], acc[i][2], acc[i][3]);
        *(float4*)(cp + 4) = make_float4(acc[i][4], acc[i][5], acc[i][6], acc[i][7]);
    }
}

// ---------------------------------------------------------------------------
// FP32 flash attention, causal. One CTA = (64 q-rows) x (one head).
// Tiles 64x64, 256 threads = 16x16, each thread a 4x4 micro-tile.
// Smem rows are 64 floats with a 16B-granularity XOR swizzle so every
// float4 access pattern below is bank-conflict-free.
// ---------------------------------------------------------------------------
__device__ __forceinline__ int swz4(int r, int k) {   // k multiple of 4
    return r * 64 + ((((k >> 2) ^ (r >> 2)) & 15) << 2);
}
__device__ __forceinline__ int swz1(int r, int k) {   // arbitrary k
    return r * 64 + ((((k >> 2) ^ (r >> 2)) & 15) << 2) + (k & 3);
}

__global__ __launch_bounds__(256, 2) void flash_kernel(
    const float* __restrict__ Qh, const float* __restrict__ Kh,
    const float* __restrict__ Vh, float* __restrict__ Od)
{
    __shared__ float sQ[64 * 64];
    __shared__ float sKP[64 * 64];   // K tile, reused as P tile each iteration
    __shared__ float sV[64 * 64];

    const int tid = threadIdx.x;
    const int tx = tid & 15;
    const int ty = tid >> 4;
    const int h = blockIdx.y;
    const int qi = gridDim.x - 1 - blockIdx.x;   // long tiles scheduled first
    const int q0 = qi * 64;
    const int cb = h * DKH;

    // Load Q tile (swizzled)
#pragma unroll
    for (int i = 0; i < 4; i++) {
        int idx = tid + i * 256;
        int r = idx >> 4;
        int c = (idx & 15) << 2;
        *(float4*)(sQ + swz4(r, c)) =
            *(const float4*)(Qh + (q0 + r) * DMODEL + cb + c);
    }

    float m_[4], l_[4], o_[4][4];
#pragma unroll
    for (int i = 0; i < 4; i++) {
        m_[i] = -3.0e38f; l_[i] = 0.f;
#pragma unroll
        for (int j = 0; j < 4; j++) o_[i][j] = 0.f;
    }

    for (int kt = 0; kt <= qi; kt++) {
        const int s0 = kt * 64;
        __syncthreads();   // prev iteration done reading sKP/sV (also covers sQ init)
#pragma unroll
        for (int i = 0; i < 4; i++) {
            int idx = tid + i * 256;
            int r = idx >> 4;
            int c = (idx & 15) << 2;
            *(float4*)(sKP + swz4(r, c)) =
                *(const float4*)(Kh + (s0 + r) * DMODEL + cb + c);
            *(float4*)(sV + swz4(r, c)) =
                *(const float4*)(Vh + (s0 + r) * DMODEL + cb + c);
        }
        __syncthreads();

        // S = Q K^T (4x4 per thread, dot-product over k in float4 steps)
        float s[4][4];
#pragma unroll
        for (int i = 0; i < 4; i++)
#pragma unroll
            for (int j = 0; j < 4; j++) s[i][j] = 0.f;

#pragma unroll 4
        for (int k = 0; k < 64; k += 4) {
            float qv[4][4], kv[4][4];
#pragma unroll
            for (int i = 0; i < 4; i++)
                *(float4*)qv[i] = *(const float4*)(sQ + swz4(4 * ty + i, k));
#pragma unroll
            for (int j = 0; j < 4; j++)
                *(float4*)kv[j] = *(const float4*)(sKP + swz4(4 * tx + j, k));
#pragma unroll
            for (int i = 0; i < 4; i++)
#pragma unroll
                for (int j = 0; j < 4; j++)
#pragma unroll
                    for (int kk = 0; kk < 4; kk++)
                        s[i][j] = fmaf(qv[i][kk], kv[j][kk], s[i][j]);
        }

        // Scale + causal mask (reference sets masked entries to exactly -1e9)
        const bool diag = (kt == qi);
#pragma unroll
        for (int i = 0; i < 4; i++)
#pragma unroll
            for (int j = 0; j < 4; j++) {
                float v = s[i][j] * 0.125f;
                if (diag && (4 * tx + j > 4 * ty + i)) v = -1e9f;
                s[i][j] = v;
            }

        // Row max across the 16 tx-threads (half-warp shuffles)
        float rm[4];
#pragma unroll
        for (int i = 0; i < 4; i++)
            rm[i] = fmaxf(fmaxf(s[i][0], s[i][1]), fmaxf(s[i][2], s[i][3]));
#pragma unroll
        for (int off = 1; off < 16; off <<= 1)
#pragma unroll
            for (int i = 0; i < 4; i++)
                rm[i] = fmaxf(rm[i], __shfl_xor_sync(0xffffffffu, rm[i], off));

        float al[4];
#pragma unroll
        for (int i = 0; i < 4; i++) {
            float mn = fmaxf(m_[i], rm[i]);
            al[i] = __expf(m_[i] - mn);
            m_[i] = mn;
        }

        // P = exp(S - m), row sums
        float rs[4];
#pragma unroll
        for (int i = 0; i < 4; i++) {
            rs[i] = 0.f;
#pragma unroll
            for (int j = 0; j < 4; j++) {
                s[i][j] = __expf(s[i][j] - m_[i]);
                rs[i] += s[i][j];
            }
        }
#pragma unroll
        for (int off = 1; off < 16; off <<= 1)
#pragma unroll
            for (int i = 0; i < 4; i++)
                rs[i] += __shfl_xor_sync(0xffffffffu, rs[i], off);

#pragma unroll
        for (int i = 0; i < 4; i++) {
            l_[i] = l_[i] * al[i] + rs[i];
#pragma unroll
            for (int j = 0; j < 4; j++) o_[i][j] *= al[i];
        }

        __syncthreads();   // everyone done reading K from sKP
#pragma unroll
        for (int i = 0; i < 4; i++)
#pragma unroll
            for (int j = 0; j < 4; j++)
                sKP[swz1(4 * ty + i, 4 * tx + j)] = s[i][j];   // P[r][sc]
        __syncthreads();

        // O += P @ V
#pragma unroll 4
        for (int sc = 0; sc < 64; sc += 4) {
            float p[4][4], v[4][4];
#pragma unroll
            for (int i = 0; i < 4; i++)
                *(float4*)p[i] = *(const float4*)(sKP + swz4(4 * ty + i, sc));
#pragma unroll
            for (int kk = 0; kk < 4; kk++)
                *(float4*)v[kk] = *(const float4*)(sV + swz4(sc + kk, 4 * tx));
#pragma unroll
            for (int i = 0; i < 4; i++)
#pragma unroll
                for (int j = 0; j < 4; j++)
#pragma unroll
                    for (int kk = 0; kk < 4; kk++)
                        o_[i][j] = fmaf(p[i][kk], v[kk][j], o_[i][j]);
        }
    }

    // Normalize and write head output into concat layout [s][h*64+c]
#pragma unroll
    for (int i = 0; i < 4; i++) {
        float inv = 1.0f / l_[i];
        int r = q0 + 4 * ty + i;
        *(float4*)(Od + r * DMODEL + cb + 4 * tx) =
            make_float4(o_[i][0] * inv, o_[i][1] * inv,
                        o_[i][2] * inv, o_[i][3] * inv);
    }
}

// ---------------------------------------------------------------------------
extern "C" void kernel_launch(void* const* d_in, const int* in_sizes, int n_in,
                              void* d_out, int out_size)
{
    const float* Q  = (const float*)d_in[0];
    const float* K  = (const float*)d_in[1];
    const float* V  = (const float*)d_in[2];
    const float* WQ = (const float*)d_in[3];
    const float* WK = (const float*)d_in[4];
    const float* WV = (const float*)d_in[5];
    const float* WO = (const float*)d_in[6];
    float* out = (float*)d_out;

    float *qh, *kh, *vh, *hd;
    cudaGetSymbolAddress((void**)&qh, g_Qh);
    cudaGetSymbolAddress((void**)&kh, g_Kh);
    cudaGetSymbolAddress((void**)&vh, g_Vh);
    cudaGetSymbolAddress((void**)&hd, g_Hd);

    dim3 gg(DMODEL / 128, SEQL / 128);   // (8, 32)
    sgemm_kernel<<<gg, 256>>>(Q, WQ, qh, 1);
    sgemm_kernel<<<gg, 256>>>(K, WK, kh, 1);
    sgemm_kernel<<<gg, 256>>>(V, WV, vh, 1);

    flash_kernel<<<dim3(SEQL / 64, NH), 256>>>(qh, kh, vh, hd);

    sgemm_kernel<<<gg, 256>>>(hd, WO, out, 0);
}

// round 2
// speedup vs baseline: 1.1533x; 1.1533x over previous
#include <cuda_runtime.h>

#define SEQL 4096
#define DMODEL 1024
#define NH 16
#define DKH 64

// Scratch (allocation-free rule: static device globals)
static __device__ float g_Qh[SEQL * DMODEL];
static __device__ float g_Kh[SEQL * DMODEL];
static __device__ float g_Vh[SEQL * DMODEL];
static __device__ float g_Hd[SEQL * DMODEL];

typedef unsigned long long ull;

// Packed fp32x2 helpers (Blackwell FFMA2 path — full fp32 precision, 2 lanes/op)
__device__ __forceinline__ void fma2(ull& d, ull a, ull b) {
    asm("fma.rn.f32x2 %0, %1, %2, %0;" : "+l"(d) : "l"(a), "l"(b));
}
__device__ __forceinline__ void mul2(ull& d, ull a) {
    asm("mul.rn.f32x2 %0, %0, %1;" : "+l"(d) : "l"(a));
}
__device__ __forceinline__ ull pack2(float lo, float hi) {
    ull r; asm("mov.b64 %0, {%1, %2};" : "=l"(r) : "f"(lo), "f"(hi)); return r;
}
__device__ __forceinline__ float2 unpack2(ull v) {
    float2 f; asm("mov.b64 {%0, %1}, %2;" : "=f"(f.x), "=f"(f.y) : "l"(v)); return f;
}

// ---------------------------------------------------------------------------
// FP32 SGEMM with packed f32x2 accumulation.
// C[4096,1024] = A[4096,1024] @ B[1024,1024]
// blockedB=1: B is W[h][d][k] head-blocked; blockedB=0: row-major.
// 128x128 tile, BK=8, 256 threads, 8x8 micro-tile (as 8x4 packed pairs).
// ---------------------------------------------------------------------------
__global__ __launch_bounds__(256, 2) void sgemm_kernel(
    const float* __restrict__ A, const float* __restrict__ B,
    float* __restrict__ C, int blockedB)
{
    __shared__ float As[8 * 128];   // As[k][m] (transposed)
    __shared__ float Bs[8 * 128];   // Bs[k][n]
    const int tid = threadIdx.x;
    const int tx = tid & 15;
    const int ty = tid >> 4;
    const int m0 = blockIdx.y * 128;
    const int n0 = blockIdx.x * 128;

    const int ar = tid >> 1;          // 0..127 row within A tile
    const int ac = (tid & 1) * 4;     // 0 or 4 (k offset)
    const int bk = tid >> 5;          // 0..7   k row within B tile
    const int bn = (tid & 31) * 4;    // 0..124 col within B tile
    const int bcol = n0 + bn;

    ull acc2[8][4];                   // acc2[i][j2] packs columns (2*j2, 2*j2+1)
#pragma unroll
    for (int i = 0; i < 8; i++)
#pragma unroll
        for (int j = 0; j < 4; j++) acc2[i][j] = 0ULL;

    for (int k0 = 0; k0 < DMODEL; k0 += 8) {
        float4 av = *(const float4*)(A + (m0 + ar) * DMODEL + k0 + ac);
        const float* bp = blockedB
            ? (B + (bcol >> 6) * (DMODEL * DKH) + (k0 + bk) * DKH + (bcol & 63))
            : (B + (k0 + bk) * DMODEL + bcol);
        float4 bv = *(const float4*)bp;

        As[(ac + 0) * 128 + ar] = av.x;
        As[(ac + 1) * 128 + ar] = av.y;
        As[(ac + 2) * 128 + ar] = av.z;
        As[(ac + 3) * 128 + ar] = av.w;
        *(float4*)(Bs + bk * 128 + bn) = bv;
        __syncthreads();

#pragma unroll
        for (int kk = 0; kk < 8; kk++) {
            float a[8];
            *(float4*)&a[0] = *(const float4*)(As + kk * 128 + ty * 8);
            *(float4*)&a[4] = *(const float4*)(As + kk * 128 + ty * 8 + 4);
            ulonglong2 b0 = *(const ulonglong2*)(Bs + kk * 128 + tx * 8);
            ulonglong2 b1 = *(const ulonglong2*)(Bs + kk * 128 + tx * 8 + 4);
#pragma unroll
            for (int i = 0; i < 8; i++) {
                ull pa = pack2(a[i], a[i]);
                fma2(acc2[i][0], pa, b0.x);
                fma2(acc2[i][1], pa, b0.y);
                fma2(acc2[i][2], pa, b1.x);
                fma2(acc2[i][3], pa, b1.y);
            }
        }
        __syncthreads();
    }

#pragma unroll
    for (int i = 0; i < 8; i++) {
        float2 c0 = unpack2(acc2[i][0]);
        float2 c1 = unpack2(acc2[i][1]);
        float2 c2 = unpack2(acc2[i][2]);
        float2 c3 = unpack2(acc2[i][3]);
        float* cp = C + (m0 + ty * 8 + i) * DMODEL + n0 + tx * 8;
        *(float4*)cp       = make_float4(c0.x, c0.y, c1.x, c1.y);
        *(float4*)(cp + 4) = make_float4(c2.x, c2.y, c3.x, c3.y);
    }
}

// ---------------------------------------------------------------------------
// FP32 flash attention, causal. One CTA = 64 q-rows x one head.
// 64x64 tiles, 256 threads (16x16), 4x4 micro-tile, packed f32x2 FMAs.
// Layouts (all conflict-free, addresses affine in compile-time constants):
//   sQ : plain [s][d] stride 64 (reads are half-warp broadcasts)
//   sKP: K rotated  phys(s,d) = s*64 + ((d + 4*((s>>2)&7)) & 63); later P plain
//   sVt: V transposed+rotated phys(d,s) = d*64 + ((s + 4*((d>>2)&7)) & 63)
// ---------------------------------------------------------------------------
__global__ __launch_bounds__(256, 2) void flash_kernel(
    const float* __restrict__ Qh, const float* __restrict__ Kh,
    const float* __restrict__ Vh, float* __restrict__ Od)
{
    __shared__ float sQ[64 * 64];
    __shared__ float sKP[64 * 64];   // K tile (rotated), reused as P tile (plain)
    __shared__ float sVt[64 * 64];   // V transposed (rotated)

    const int tid = threadIdx.x;
    const int tx = tid & 15;
    const int ty = tid >> 4;
    const int h = blockIdx.y;
    const int qi = gridDim.x - 1 - blockIdx.x;   // long tiles scheduled first
    const int q0 = qi * 64;
    const int cb = h * DKH;
    const int rot = 4 * (tx & 7);    // rotation offset for K / Vt reads

    // Load Q tile (plain)
#pragma unroll
    for (int i = 0; i < 4; i++) {
        int idx = tid + i * 256;
        int r = idx >> 4;
        int c = (idx & 15) << 2;
        *(float4*)(sQ + r * 64 + c) =
            *(const float4*)(Qh + (q0 + r) * DMODEL + cb + c);
    }

    float m_[4], l_[4];
    ull o2[4][4];
#pragma unroll
    for (int i = 0; i < 4; i++) {
        m_[i] = -3.0e38f; l_[i] = 0.f;
#pragma unroll
        for (int j = 0; j < 4; j++) o2[i][j] = 0ULL;
    }

    for (int kt = 0; kt <= qi; kt++) {
        const int s0 = kt * 64;
        __syncthreads();   // previous iteration done reading sKP(P)/sVt
#pragma unroll
        for (int i = 0; i < 4; i++) {
            int idx = tid + i * 256;
            int r = idx >> 4;
            int c = (idx & 15) << 2;
            float4 k4 = *(const float4*)(Kh + (s0 + r) * DMODEL + cb + c);
            *(float4*)(sKP + r * 64 + ((c + 4 * ((r >> 2) & 7)) & 63)) = k4;
            float4 v4 = *(const float4*)(Vh + (s0 + r) * DMODEL + cb + c);
            int offv = (r + 4 * ((c >> 2) & 7)) & 63;   // same for c..c+3
            sVt[(c + 0) * 64 + offv] = v4.x;
            sVt[(c + 1) * 64 + offv] = v4.y;
            sVt[(c + 2) * 64 + offv] = v4.z;
            sVt[(c + 3) * 64 + offv] = v4.w;
        }
        __syncthreads();

        // S = Q K^T, packed pairs along the d reduction dim
        ull s2[4][4];
#pragma unroll
        for (int i = 0; i < 4; i++)
#pragma unroll
            for (int j = 0; j < 4; j++) s2[i][j] = 0ULL;

#pragma unroll
        for (int k = 0; k < 64; k += 4) {
            const int offk = (k + rot) & 63;
            ulonglong2 q[4], kv[4];
#pragma unroll
            for (int i = 0; i < 4; i++)
                q[i] = *(const ulonglong2*)(sQ + (4 * ty + i) * 64 + k);
#pragma unroll
            for (int j = 0; j < 4; j++)
                kv[j] = *(const ulonglong2*)(sKP + (4 * tx + j) * 64 + offk);
#pragma unroll
            for (int i = 0; i < 4; i++)
#pragma unroll
                for (int j = 0; j < 4; j++) {
                    fma2(s2[i][j], q[i].x, kv[j].x);
                    fma2(s2[i][j], q[i].y, kv[j].y);
                }
        }

        // Fold pairs, scale, causal mask
        float s[4][4];
        const bool diag = (kt == qi);
#pragma unroll
        for (int i = 0; i < 4; i++)
#pragma unroll
            for (int j = 0; j < 4; j++) {
                float2 f = unpack2(s2[i][j]);
                float v = (f.x + f.y) * 0.125f;
                if (diag && (4 * tx + j > 4 * ty + i)) v = -1e9f;
                s[i][j] = v;
            }

        // Row max across the 16 tx-threads
        float rm[4];
#pragma unroll
        for (int i = 0; i < 4; i++)
            rm[i] = fmaxf(fmaxf(s[i][0], s[i][1]), fmaxf(s[i][2], s[i][3]));
#pragma unroll
        for (int off = 1; off < 16; off <<= 1)
#pragma unroll
            for (int i = 0; i < 4; i++)
                rm[i] = fmaxf(rm[i], __shfl_xor_sync(0xffffffffu, rm[i], off));

        float al[4];
#pragma unroll
        for (int i = 0; i < 4; i++) {
            float mn = fmaxf(m_[i], rm[i]);
            al[i] = __expf(m_[i] - mn);
            m_[i] = mn;
        }

        // P = exp(S - m), row sums
        float rs[4];
#pragma unroll
        for (int i = 0; i < 4; i++) {
            rs[i] = 0.f;
#pragma unroll
            for (int j = 0; j < 4; j++) {
                s[i][j] = __expf(s[i][j] - m_[i]);
                rs[i] += s[i][j];
            }
        }
#pragma unroll
        for (int off = 1; off < 16; off <<= 1)
#pragma unroll
            for (int i = 0; i < 4; i++)
                rs[i] += __shfl_xor_sync(0xffffffffu, rs[i], off);

#pragma unroll
        for (int i = 0; i < 4; i++) {
            l_[i] = l_[i] * al[i] + rs[i];
            ull al2 = pack2(al[i], al[i]);
#pragma unroll
            for (int j = 0; j < 4; j++) mul2(o2[i][j], al2);
        }

        __syncthreads();   // everyone done reading K from sKP
#pragma unroll
        for (int i = 0; i < 4; i++)
            *(float4*)(sKP + (4 * ty + i) * 64 + 4 * tx) =
                make_float4(s[i][0], s[i][1], s[i][2], s[i][3]);
        __syncthreads();

        // O += P @ V, packed pairs along the s reduction dim
#pragma unroll
        for (int sc = 0; sc < 64; sc += 4) {
            const int offv = (sc + rot) & 63;
            ulonglong2 p[4], v[4];
#pragma unroll
            for (int i = 0; i < 4; i++)
                p[i] = *(const ulonglong2*)(sKP + (4 * ty + i) * 64 + sc);
#pragma unroll
            for (int j = 0; j < 4; j++)
                v[j] = *(const ulonglong2*)(sVt + (4 * tx + j) * 64 + offv);
#pragma unroll
            for (int i = 0; i < 4; i++)
#pragma unroll
                for (int j = 0; j < 4; j++) {
                    fma2(o2[i][j], p[i].x, v[j].x);
                    fma2(o2[i][j], p[i].y, v[j].y);
                }
        }
    }

    // Normalize, fold pairs, write concat layout [s][h*64+c]
#pragma unroll
    for (int i = 0; i < 4; i++) {
        float inv = 1.0f / l_[i];
        float o[4];
#pragma unroll
        for (int j = 0; j < 4; j++) {
            float2 f = unpack2(o2[i][j]);
            o[j] = (f.x + f.y) * inv;
        }
        int r = q0 + 4 * ty + i;
        *(float4*)(Od + r * DMODEL + cb + 4 * tx) =
            make_float4(o[0], o[1], o[2], o[3]);
    }
}

// ---------------------------------------------------------------------------
extern "C" void kernel_launch(void* const* d_in, const int* in_sizes, int n_in,
                              void* d_out, int out_size)
{
    const float* Q  = (const float*)d_in[0];
    const float* K  = (const float*)d_in[1];
    const float* V  = (const float*)d_in[2];
    const float* WQ = (const float*)d_in[3];
    const float* WK = (const float*)d_in[4];
    const float* WV = (const float*)d_in[5];
    const float* WO = (const float*)d_in[6];
    float* out = (float*)d_out;

    float *qh, *kh, *vh, *hd;
    cudaGetSymbolAddress((void**)&qh, g_Qh);
    cudaGetSymbolAddress((void**)&kh, g_Kh);
    cudaGetSymbolAddress((void**)&vh, g_Vh);
    cudaGetSymbolAddress((void**)&hd, g_Hd);

    dim3 gg(DMODEL / 128, SEQL / 128);   // (8, 32)
    sgemm_kernel<<<gg, 256>>>(Q, WQ, qh, 1);
    sgemm_kernel<<<gg, 256>>>(K, WK, kh, 1);
    sgemm_kernel<<<gg, 256>>>(V, WV, vh, 1);

    flash_kernel<<<dim3(SEQL / 64, NH), 256>>>(qh, kh, vh, hd);

    sgemm_kernel<<<gg, 256>>>(hd, WO, out, 0);
}

// round 4
// speedup vs baseline: 1.5440x; 1.3387x over previous
#include <cuda_runtime.h>
#include <cuda_bf16.h>
#include <cstdint>

#define SEQL 4096
#define DMODEL 1024
#define NH 16
#define DKH 64

// Scratch (allocation-free rule: static device globals)
static __device__ float g_Qh[SEQL * DMODEL];
static __device__ float g_Kh[SEQL * DMODEL];
static __device__ float g_Vh[SEQL * DMODEL];
static __device__ float g_Hd[SEQL * DMODEL];
static __device__ __nv_bfloat16 g_Ah[SEQL * DMODEL];
static __device__ __nv_bfloat16 g_Al[SEQL * DMODEL];
static __device__ __nv_bfloat16 g_Bth[DMODEL * DMODEL];
static __device__ __nv_bfloat16 g_Btl[DMODEL * DMODEL];

typedef unsigned long long ull;

// ---------------- low-level helpers (base PTX only, no 'a' features) -------
__device__ __forceinline__ uint32_t smem_u32(const void* p) {
    uint32_t a;
    asm("{ .reg .u64 t; cvta.to.shared.u64 t, %1; cvt.u32.u64 %0, t; }" : "=r"(a) : "l"(p));
    return a;
}
__device__ __forceinline__ void cp16(uint32_t dst, const void* src) {
    asm volatile("cp.async.cg.shared.global [%0], [%1], 16;" :: "r"(dst), "l"(src));
}
__device__ __forceinline__ void cp_commit() {
    asm volatile("cp.async.commit_group;" ::: "memory");
}
__device__ __forceinline__ void ldmx4(uint32_t* r, uint32_t addr) {
    asm volatile("ldmatrix.sync.aligned.m8n8.x4.shared.b16 {%0,%1,%2,%3}, [%4];"
                 : "=r"(r[0]), "=r"(r[1]), "=r"(r[2]), "=r"(r[3]) : "r"(addr));
}
__device__ __forceinline__ void mma16816(float* c, const uint32_t* a, const uint32_t* b) {
    asm volatile(
        "mma.sync.aligned.m16n8k16.row.col.f32.bf16.bf16.f32 "
        "{%0,%1,%2,%3}, {%4,%5,%6,%7}, {%8,%9}, {%0,%1,%2,%3};"
        : "+f"(c[0]), "+f"(c[1]), "+f"(c[2]), "+f"(c[3])
        : "r"(a[0]), "r"(a[1]), "r"(a[2]), "r"(a[3]), "r"(b[0]), "r"(b[1]));
}

// Packed fp32x2 helpers (flash kernel)
__device__ __forceinline__ void fma2(ull& d, ull a, ull b) {
    asm("fma.rn.f32x2 %0, %1, %2, %0;" : "+l"(d) : "l"(a), "l"(b));
}
__device__ __forceinline__ void mul2(ull& d, ull a) {
    asm("mul.rn.f32x2 %0, %0, %1;" : "+l"(d) : "l"(a));
}
__device__ __forceinline__ ull pack2(float lo, float hi) {
    ull r; asm("mov.b64 %0, {%1, %2};" : "=l"(r) : "f"(lo), "f"(hi)); return r;
}
__device__ __forceinline__ float2 unpack2(ull v) {
    float2 f; asm("mov.b64 {%0, %1}, %2;" : "=f"(f.x), "=f"(f.y) : "l"(v)); return f;
}

// ---------------------------------------------------------------------------
// Split fp32 -> bf16 hi/lo.  X[4096,1024] row-major -> H,L same layout.
// ---------------------------------------------------------------------------
__global__ void split_x_kernel(const float* __restrict__ X,
                               __nv_bfloat16* __restrict__ H,
                               __nv_bfloat16* __restrict__ L)
{
    int i = (blockIdx.x * blockDim.x + threadIdx.x) * 4;
    float4 v = *(const float4*)(X + i);
    float vv[4] = {v.x, v.y, v.z, v.w};
    __nv_bfloat16 h[4], l[4];
#pragma unroll
    for (int j = 0; j < 4; j++) {
        h[j] = __float2bfloat16_rn(vv[j]);
        l[j] = __float2bfloat16_rn(vv[j] - __bfloat162float(h[j]));
    }
    *(__nv_bfloat162*)(H + i)     = __nv_bfloat162(h[0], h[1]);
    *(__nv_bfloat162*)(H + i + 2) = __nv_bfloat162(h[2], h[3]);
    *(__nv_bfloat162*)(L + i)     = __nv_bfloat162(l[0], l[1]);
    *(__nv_bfloat162*)(L + i + 2) = __nv_bfloat162(l[2], l[3]);
}

// ---------------------------------------------------------------------------
// Split weight -> Bt[n][k] bf16 hi/lo ([N=1024, K=1024] K-contiguous).
// blocked=1: W[h][d][k] head-blocked (Bt[n][k] = W[n>>6][k][n&63])
// blocked=0: W[k][n] row-major      (Bt[n][k] = W[k*1024+n])
// ---------------------------------------------------------------------------
__global__ void split_w_kernel(const float* __restrict__ W,
                               __nv_bfloat16* __restrict__ H,
                               __nv_bfloat16* __restrict__ L, int blocked)
{
    int idx = blockIdx.x * blockDim.x + threadIdx.x;   // = n*1024 + k
    int n = idx >> 10, k = idx & 1023;
    float v = blocked ? W[(n >> 6) * (DMODEL * DKH) + k * DKH + (n & 63)]
                      : W[k * DMODEL + n];
    __nv_bfloat16 h = __float2bfloat16_rn(v);
    H[idx] = h;
    L[idx] = __float2bfloat16_rn(v - __bfloat162float(h));
}

// ---------------------------------------------------------------------------
// bf16x3 GEMM on mma.sync (HMMA):  C[4096,1024] = A @ Bt^T (fp32 accuracy).
// CTA tile 128x128, BK=32, 256 threads / 8 warps, warp tile 64x32.
// Smem rows padded to 40 bf16 (80B) -> conflict-free ldmatrix.
// 2-stage cp.async pipeline.
// ---------------------------------------------------------------------------
#define GST 40                      // smem row stride (bf16 elems)
#define GTILE (128 * GST * 2)       // 10240 bytes per tile
#define GSTAGE (4 * GTILE)          // Ah, Al, Bh, Bl
#define GSMEM (2 * GSTAGE)          // 81920 bytes

__global__ __launch_bounds__(256, 2) void tc_gemm_kernel(
    const __nv_bfloat16* __restrict__ Ah, const __nv_bfloat16* __restrict__ Al,
    const __nv_bfloat16* __restrict__ Bh, const __nv_bfloat16* __restrict__ Bl,
    float* __restrict__ C)
{
    extern __shared__ char smem[];
    const uint32_t sb = smem_u32(smem);
    const int tid = threadIdx.x;
    const int wid = tid >> 5, lane = tid & 31;
    const int m0 = blockIdx.y * 128;
    const int n0 = blockIdx.x * 128;
    const int wm0 = (wid & 1) * 64;      // warp m offset
    const int wn0 = (wid >> 1) * 32;     // warp n offset

    float acc[4][4][4];
#pragma unroll
    for (int i = 0; i < 4; i++)
#pragma unroll
        for (int j = 0; j < 4; j++)
#pragma unroll
            for (int t = 0; t < 4; t++) acc[i][j][t] = 0.f;

    // per-thread load slots: 2 chunks per tile, 4 tiles
    const int c0r = tid >> 1, c0c = (tid & 1) * 2;        // chunks tid*2, tid*2+1
    // chunk idx i in [0,512): row=i>>2, col16=i&3.  thread covers i=2*tid, 2*tid+1
    const int lr = (2 * tid) >> 2;        // row for both chunks (same row)
    const int lc = (2 * tid) & 3;         // first col16
    (void)c0r; (void)c0c;

    auto load_stage = [&](int st, int k0) {
        uint32_t base = sb + st * GSTAGE;
        const __nv_bfloat16* ga = Ah + (m0 + lr) * DMODEL + k0 + lc * 8;
        const __nv_bfloat16* gal = Al + (m0 + lr) * DMODEL + k0 + lc * 8;
        const __nv_bfloat16* gb = Bh + (n0 + lr) * DMODEL + k0 + lc * 8;
        const __nv_bfloat16* gbl = Bl + (n0 + lr) * DMODEL + k0 + lc * 8;
        uint32_t so = lr * (GST * 2) + lc * 16;
        cp16(base + so, ga);             cp16(base + so + 16, ga + 8);
        cp16(base + GTILE + so, gal);    cp16(base + GTILE + so + 16, gal + 8);
        cp16(base + 2 * GTILE + so, gb); cp16(base + 2 * GTILE + so + 16, gb + 8);
        cp16(base + 3 * GTILE + so, gbl);cp16(base + 3 * GTILE + so + 16, gbl + 8);
        cp_commit();
    };

    load_stage(0, 0);

    for (int kc = 0; kc < 32; kc++) {
        if (kc + 1 < 32) load_stage((kc + 1) & 1, (kc + 1) * 32);
        if (kc + 1 < 32) asm volatile("cp.async.wait_group 1;" ::: "memory");
        else             asm volatile("cp.async.wait_group 0;" ::: "memory");
        __syncthreads();

        uint32_t base = sb + (kc & 1) * GSTAGE;
#pragma unroll
        for (int k16 = 0; k16 < 32; k16 += 16) {
            // B fragments: 2 x4-ldmatrix per operand cover 4 n-tiles
            uint32_t bh[4][2], bl[4][2];
#pragma unroll
            for (int bt = 0; bt < 2; bt++) {
                int nrow = wn0 + bt * 16 + (lane & 7) + ((lane >> 4) << 3);
                int kcol = k16 + ((lane >> 3) & 1) * 8;
                uint32_t ad = base + 2 * GTILE + nrow * (GST * 2) + kcol * 2;
                uint32_t r[4];
                ldmx4(r, ad);
                bh[bt * 2][0] = r[0]; bh[bt * 2][1] = r[1];
                bh[bt * 2 + 1][0] = r[2]; bh[bt * 2 + 1][1] = r[3];
                ldmx4(r, ad + GTILE);
                bl[bt * 2][0] = r[0]; bl[bt * 2][1] = r[1];
                bl[bt * 2 + 1][0] = r[2]; bl[bt * 2 + 1][1] = r[3];
            }
#pragma unroll
            for (int mt = 0; mt < 4; mt++) {
                int mrow = wm0 + mt * 16 + (lane & 15);
                int kcol = k16 + (lane >> 4) * 8;
                uint32_t ad = base + mrow * (GST * 2) + kcol * 2;
                uint32_t ah[4], al[4];
                ldmx4(ah, ad);
                ldmx4(al, ad + GTILE);
#pragma unroll
                for (int nt = 0; nt < 4; nt++) {
                    mma16816(acc[mt][nt], ah, bh[nt]);
                    mma16816(acc[mt][nt], ah, bl[nt]);
                    mma16816(acc[mt][nt], al, bh[nt]);
                }
            }
        }
        __syncthreads();
    }

    // Epilogue: fragment layout c0,c1=(r, c),(r, c+1); c2,c3=(r+8, ...)
    const int er = lane >> 2;
    const int ec = 2 * (lane & 3);
#pragma unroll
    for (int mt = 0; mt < 4; mt++) {
#pragma unroll
        for (int nt = 0; nt < 4; nt++) {
            int r = m0 + wm0 + mt * 16 + er;
            int c = n0 + wn0 + nt * 8 + ec;
            *(float2*)(C + r * DMODEL + c) = make_float2(acc[mt][nt][0], acc[mt][nt][1]);
            *(float2*)(C + (r + 8) * DMODEL + c) = make_float2(acc[mt][nt][2], acc[mt][nt][3]);
        }
    }
}

// ---------------------------------------------------------------------------
// FP32 flash attention, causal (unchanged from R2). One CTA = 64 q-rows x head.
// ---------------------------------------------------------------------------
__global__ __launch_bounds__(256, 2) void flash_kernel(
    const float* __restrict__ Qh, const float* __restrict__ Kh,
    const float* __restrict__ Vh, float* __restrict__ Od)
{
    __shared__ float sQ[64 * 64];
    __shared__ float sKP[64 * 64];
    __shared__ float sVt[64 * 64];

    const int tid = threadIdx.x;
    const int tx = tid & 15;
    const int ty = tid >> 4;
    const int h = blockIdx.y;
    const int qi = gridDim.x - 1 - blockIdx.x;
    const int q0 = qi * 64;
    const int cb = h * DKH;
    const int rot = 4 * (tx & 7);

#pragma unroll
    for (int i = 0; i < 4; i++) {
        int idx = tid + i * 256;
        int r = idx >> 4;
        int c = (idx & 15) << 2;
        *(float4*)(sQ + r * 64 + c) =
            *(const float4*)(Qh + (q0 + r) * DMODEL + cb + c);
    }

    float m_[4], l_[4];
    ull o2[4][4];
#pragma unroll
    for (int i = 0; i < 4; i++) {
        m_[i] = -3.0e38f; l_[i] = 0.f;
#pragma unroll
        for (int j = 0; j < 4; j++) o2[i][j] = 0ULL;
    }

    for (int kt = 0; kt <= qi; kt++) {
        const int s0 = kt * 64;
        __syncthreads();
#pragma unroll
        for (int i = 0; i < 4; i++) {
            int idx = tid + i * 256;
            int r = idx >> 4;
            int c = (idx & 15) << 2;
            float4 k4 = *(const float4*)(Kh + (s0 + r) * DMODEL + cb + c);
            *(float4*)(sKP + r * 64 + ((c + 4 * ((r >> 2) & 7)) & 63)) = k4;
            float4 v4 = *(const float4*)(Vh + (s0 + r) * DMODEL + cb + c);
            int offv = (r + 4 * ((c >> 2) & 7)) & 63;
            sVt[(c + 0) * 64 + offv] = v4.x;
            sVt[(c + 1) * 64 + offv] = v4.y;
            sVt[(c + 2) * 64 + offv] = v4.z;
            sVt[(c + 3) * 64 + offv] = v4.w;
        }
        __syncthreads();

        ull s2[4][4];
#pragma unroll
        for (int i = 0; i < 4; i++)
#pragma unroll
            for (int j = 0; j < 4; j++) s2[i][j] = 0ULL;

#pragma unroll
        for (int k = 0; k < 64; k += 4) {
            const int offk = (k + rot) & 63;
            ulonglong2 q[4], kv[4];
#pragma unroll
            for (int i = 0; i < 4; i++)
                q[i] = *(const ulonglong2*)(sQ + (4 * ty + i) * 64 + k);
#pragma unroll
            for (int j = 0; j < 4; j++)
                kv[j] = *(const ulonglong2*)(sKP + (4 * tx + j) * 64 + offk);
#pragma unroll
            for (int i = 0; i < 4; i++)
#pragma unroll
                for (int j = 0; j < 4; j++) {
                    fma2(s2[i][j], q[i].x, kv[j].x);
                    fma2(s2[i][j], q[i].y, kv[j].y);
                }
        }

        float s[4][4];
        const bool diag = (kt == qi);
#pragma unroll
        for (int i = 0; i < 4; i++)
#pragma unroll
            for (int j = 0; j < 4; j++) {
                float2 f = unpack2(s2[i][j]);
                float v = (f.x + f.y) * 0.125f;
                if (diag && (4 * tx + j > 4 * ty + i)) v = -1e9f;
                s[i][j] = v;
            }

        float rm[4];
#pragma unroll
        for (int i = 0; i < 4; i++)
            rm[i] = fmaxf(fmaxf(s[i][0], s[i][1]), fmaxf(s[i][2], s[i][3]));
#pragma unroll
        for (int off = 1; off < 16; off <<= 1)
#pragma unroll
            for (int i = 0; i < 4; i++)
                rm[i] = fmaxf(rm[i], __shfl_xor_sync(0xffffffffu, rm[i], off));

        float al[4];
#pragma unroll
        for (int i = 0; i < 4; i++) {
            float mn = fmaxf(m_[i], rm[i]);
            al[i] = __expf(m_[i] - mn);
            m_[i] = mn;
        }

        float rs[4];
#pragma unroll
        for (int i = 0; i < 4; i++) {
            rs[i] = 0.f;
#pragma unroll
            for (int j = 0; j < 4; j++) {
                s[i][j] = __expf(s[i][j] - m_[i]);
                rs[i] += s[i][j];
            }
        }
#pragma unroll
        for (int off = 1; off < 16; off <<= 1)
#pragma unroll
            for (int i = 0; i < 4; i++)
                rs[i] += __shfl_xor_sync(0xffffffffu, rs[i], off);

#pragma unroll
        for (int i = 0; i < 4; i++) {
            l_[i] = l_[i] * al[i] + rs[i];
            ull al2 = pack2(al[i], al[i]);
#pragma unroll
            for (int j = 0; j < 4; j++) mul2(o2[i][j], al2);
        }

        __syncthreads();
#pragma unroll
        for (int i = 0; i < 4; i++)
            *(float4*)(sKP + (4 * ty + i) * 64 + 4 * tx) =
                make_float4(s[i][0], s[i][1], s[i][2], s[i][3]);
        __syncthreads();

#pragma unroll
        for (int sc = 0; sc < 64; sc += 4) {
            const int offv = (sc + rot) & 63;
            ulonglong2 p[4], v[4];
#pragma unroll
            for (int i = 0; i < 4; i++)
                p[i] = *(const ulonglong2*)(sKP + (4 * ty + i) * 64 + sc);
#pragma unroll
            for (int j = 0; j < 4; j++)
                v[j] = *(const ulonglong2*)(sVt + (4 * tx + j) * 64 + offv);
#pragma unroll
            for (int i = 0; i < 4; i++)
#pragma unroll
                for (int j = 0; j < 4; j++) {
                    fma2(o2[i][j], p[i].x, v[j].x);
                    fma2(o2[i][j], p[i].y, v[j].y);
                }
        }
    }

#pragma unroll
    for (int i = 0; i < 4; i++) {
        float inv = 1.0f / l_[i];
        float o[4];
#pragma unroll
        for (int j = 0; j < 4; j++) {
            float2 f = unpack2(o2[i][j]);
            o[j] = (f.x + f.y) * inv;
        }
        int r = q0 + 4 * ty + i;
        *(float4*)(Od + r * DMODEL + cb + 4 * tx) =
            make_float4(o[0], o[1], o[2], o[3]);
    }
}

// ---------------------------------------------------------------------------
extern "C" void kernel_launch(void* const* d_in, const int* in_sizes, int n_in,
                              void* d_out, int out_size)
{
    const float* Q  = (const float*)d_in[0];
    const float* K  = (const float*)d_in[1];
    const float* V  = (const float*)d_in[2];
    const float* WQ = (const float*)d_in[3];
    const float* WK = (const float*)d_in[4];
    const float* WV = (const float*)d_in[5];
    const float* WO = (const float*)d_in[6];
    float* out = (float*)d_out;

    float *qh, *kh, *vh, *hd;
    __nv_bfloat16 *ah, *al, *bth, *btl;
    cudaGetSymbolAddress((void**)&qh, g_Qh);
    cudaGetSymbolAddress((void**)&kh, g_Kh);
    cudaGetSymbolAddress((void**)&vh, g_Vh);
    cudaGetSymbolAddress((void**)&hd, g_Hd);
    cudaGetSymbolAddress((void**)&ah, g_Ah);
    cudaGetSymbolAddress((void**)&al, g_Al);
    cudaGetSymbolAddress((void**)&bth, g_Bth);
    cudaGetSymbolAddress((void**)&btl, g_Btl);

    static bool attr_done = false;
    if (!attr_done) {
        cudaFuncSetAttribute(tc_gemm_kernel,
                             cudaFuncAttributeMaxDynamicSharedMemorySize, GSMEM);
        attr_done = true;
    }

    const int splitx_blocks = (SEQL * DMODEL / 4) / 256;   // 4096
    const int splitw_blocks = (DMODEL * DMODEL) / 256;     // 4096
    dim3 gg(DMODEL / 128, SEQL / 128);                     // (8, 32)

    // Q projection
    split_x_kernel<<<splitx_blocks, 256>>>(Q, ah, al);
    split_w_kernel<<<splitw_blocks, 256>>>(WQ, bth, btl, 1);
    tc_gemm_kernel<<<gg, 256, GSMEM>>>(ah, al, bth, btl, qh);
    // K projection
    split_x_kernel<<<splitx_blocks, 256>>>(K, ah, al);
    split_w_kernel<<<splitw_blocks, 256>>>(WK, bth, btl, 1);
    tc_gemm_kernel<<<gg, 256, GSMEM>>>(ah, al, bth, btl, kh);
    // V projection
    split_x_kernel<<<splitx_blocks, 256>>>(V, ah, al);
    split_w_kernel<<<splitw_blocks, 256>>>(WV, bth, btl, 1);
    tc_gemm_kernel<<<gg, 256, GSMEM>>>(ah, al, bth, btl, vh);

    flash_kernel<<<dim3(SEQL / 64, NH), 256>>>(qh, kh, vh, hd);

    // Output projection
    split_x_kernel<<<splitx_blocks, 256>>>(hd, ah, al);
    split_w_kernel<<<splitw_blocks, 256>>>(WO, bth, btl, 0);
    tc_gemm_kernel<<<gg, 256, GSMEM>>>(ah, al, bth, btl, out);
}

// round 5
// speedup vs baseline: 2.9947x; 1.9396x over previous
#include <cuda_runtime.h>
#include <cuda_bf16.h>
#include <cstdint>

#define SEQL 4096
#define DMODEL 1024
#define NH 16
#define DKH 64

// Scratch (allocation-free rule: static device globals)
static __device__ __nv_bfloat16 g_Ah[SEQL * DMODEL];
static __device__ __nv_bfloat16 g_Al[SEQL * DMODEL];
static __device__ __nv_bfloat16 g_Bth[DMODEL * DMODEL];
static __device__ __nv_bfloat16 g_Btl[DMODEL * DMODEL];
static __device__ __nv_bfloat16 g_Qhh[SEQL * DMODEL];
static __device__ __nv_bfloat16 g_Qhl[SEQL * DMODEL];
static __device__ __nv_bfloat16 g_Khh[SEQL * DMODEL];
static __device__ __nv_bfloat16 g_Khl[SEQL * DMODEL];
static __device__ __nv_bfloat16 g_Vhh[SEQL * DMODEL];
static __device__ __nv_bfloat16 g_Vhl[SEQL * DMODEL];
static __device__ __nv_bfloat16 g_Ohh[SEQL * DMODEL];
static __device__ __nv_bfloat16 g_Ohl[SEQL * DMODEL];

// ---------------- low-level helpers (base PTX only, no 'a' features) -------
__device__ __forceinline__ uint32_t smem_u32(const void* p) {
    uint32_t a;
    asm("{ .reg .u64 t; cvta.to.shared.u64 t, %1; cvt.u32.u64 %0, t; }" : "=r"(a) : "l"(p));
    return a;
}
__device__ __forceinline__ void cp16(uint32_t dst, const void* src) {
    asm volatile("cp.async.cg.shared.global [%0], [%1], 16;" :: "r"(dst), "l"(src));
}
__device__ __forceinline__ void cp_commit() {
    asm volatile("cp.async.commit_group;" ::: "memory");
}
__device__ __forceinline__ void ldmx4(uint32_t* r, uint32_t addr) {
    asm volatile("ldmatrix.sync.aligned.m8n8.x4.shared.b16 {%0,%1,%2,%3}, [%4];"
                 : "=r"(r[0]), "=r"(r[1]), "=r"(r[2]), "=r"(r[3]) : "r"(addr));
}
__device__ __forceinline__ void ldmx4t(uint32_t* r, uint32_t addr) {
    asm volatile("ldmatrix.sync.aligned.m8n8.x4.trans.shared.b16 {%0,%1,%2,%3}, [%4];"
                 : "=r"(r[0]), "=r"(r[1]), "=r"(r[2]), "=r"(r[3]) : "r"(addr));
}
__device__ __forceinline__ void mma16816(float* c, const uint32_t* a, const uint32_t* b) {
    asm volatile(
        "mma.sync.aligned.m16n8k16.row.col.f32.bf16.bf16.f32 "
        "{%0,%1,%2,%3}, {%4,%5,%6,%7}, {%8,%9}, {%0,%1,%2,%3};"
        : "+f"(c[0]), "+f"(c[1]), "+f"(c[2]), "+f"(c[3])
        : "r"(a[0]), "r"(a[1]), "r"(a[2]), "r"(a[3]), "r"(b[0]), "r"(b[1]));
}
// fp32 pair -> bf16 hi frag + bf16 residual frag (low half = first elem)
__device__ __forceinline__ void pconv(float s0, float s1, uint32_t& ph, uint32_t& pl) {
    __nv_bfloat162 h2 = __floats2bfloat162_rn(s0, s1);
    __nv_bfloat162 l2 = __floats2bfloat162_rn(s0 - __bfloat162float(h2.x),
                                              s1 - __bfloat162float(h2.y));
    ph = *(uint32_t*)&h2;
    pl = *(uint32_t*)&l2;
}

// ---------------------------------------------------------------------------
// Split fp32 -> bf16 hi/lo.  X[4096,1024] row-major -> H,L same layout.
// ---------------------------------------------------------------------------
__global__ void split_x_kernel(const float* __restrict__ X,
                               __nv_bfloat16* __restrict__ H,
                               __nv_bfloat16* __restrict__ L)
{
    int i = (blockIdx.x * blockDim.x + threadIdx.x) * 4;
    float4 v = *(const float4*)(X + i);
    float vv[4] = {v.x, v.y, v.z, v.w};
    __nv_bfloat16 h[4], l[4];
#pragma unroll
    for (int j = 0; j < 4; j++) {
        h[j] = __float2bfloat16_rn(vv[j]);
        l[j] = __float2bfloat16_rn(vv[j] - __bfloat162float(h[j]));
    }
    *(__nv_bfloat162*)(H + i)     = __nv_bfloat162(h[0], h[1]);
    *(__nv_bfloat162*)(H + i + 2) = __nv_bfloat162(h[2], h[3]);
    *(__nv_bfloat162*)(L + i)     = __nv_bfloat162(l[0], l[1]);
    *(__nv_bfloat162*)(L + i + 2) = __nv_bfloat162(l[2], l[3]);
}

// ---------------------------------------------------------------------------
// Split weight -> Bt[n][k] bf16 hi/lo ([N=1024, K=1024] K-contiguous).
// ---------------------------------------------------------------------------
__global__ void split_w_kernel(const float* __restrict__ W,
                               __nv_bfloat16* __restrict__ H,
                               __nv_bfloat16* __restrict__ L, int blocked)
{
    int idx = blockIdx.x * blockDim.x + threadIdx.x;   // = n*1024 + k
    int n = idx >> 10, k = idx & 1023;
    float v = blocked ? W[(n >> 6) * (DMODEL * DKH) + k * DKH + (n & 63)]
                      : W[k * DMODEL + n];
    __nv_bfloat16 h = __float2bfloat16_rn(v);
    H[idx] = h;
    L[idx] = __float2bfloat16_rn(v - __bfloat162float(h));
}

// ---------------------------------------------------------------------------
// bf16x3 GEMM on mma.sync:  C = A @ Bt^T.  Epilogue: fp32 (Cf) or bf16
// hi/lo split (Ch/Cl) when Ch != nullptr.
// ---------------------------------------------------------------------------
#define GST 40
#define GTILE (128 * GST * 2)
#define GSTAGE (4 * GTILE)
#define GSMEM (2 * GSTAGE)

__global__ __launch_bounds__(256, 2) void tc_gemm_kernel(
    const __nv_bfloat16* __restrict__ Ah, const __nv_bfloat16* __restrict__ Al,
    const __nv_bfloat16* __restrict__ Bh, const __nv_bfloat16* __restrict__ Bl,
    float* __restrict__ Cf,
    __nv_bfloat16* __restrict__ Ch, __nv_bfloat16* __restrict__ Cl)
{
    extern __shared__ char smem[];
    const uint32_t sb = smem_u32(smem);
    const int tid = threadIdx.x;
    const int wid = tid >> 5, lane = tid & 31;
    const int m0 = blockIdx.y * 128;
    const int n0 = blockIdx.x * 128;
    const int wm0 = (wid & 1) * 64;
    const int wn0 = (wid >> 1) * 32;

    float acc[4][4][4];
#pragma unroll
    for (int i = 0; i < 4; i++)
#pragma unroll
        for (int j = 0; j < 4; j++)
#pragma unroll
            for (int t = 0; t < 4; t++) acc[i][j][t] = 0.f;

    const int lr = (2 * tid) >> 2;
    const int lc = (2 * tid) & 3;

    auto load_stage = [&](int st, int k0) {
        uint32_t base = sb + st * GSTAGE;
        const __nv_bfloat16* ga = Ah + (m0 + lr) * DMODEL + k0 + lc * 8;
        const __nv_bfloat16* gal = Al + (m0 + lr) * DMODEL + k0 + lc * 8;
        const __nv_bfloat16* gb = Bh + (n0 + lr) * DMODEL + k0 + lc * 8;
        const __nv_bfloat16* gbl = Bl + (n0 + lr) * DMODEL + k0 + lc * 8;
        uint32_t so = lr * (GST * 2) + lc * 16;
        cp16(base + so, ga);             cp16(base + so + 16, ga + 8);
        cp16(base + GTILE + so, gal);    cp16(base + GTILE + so + 16, gal + 8);
        cp16(base + 2 * GTILE + so, gb); cp16(base + 2 * GTILE + so + 16, gb + 8);
        cp16(base + 3 * GTILE + so, gbl);cp16(base + 3 * GTILE + so + 16, gbl + 8);
        cp_commit();
    };

    load_stage(0, 0);

    for (int kc = 0; kc < 32; kc++) {
        if (kc + 1 < 32) load_stage((kc + 1) & 1, (kc + 1) * 32);
        if (kc + 1 < 32) asm volatile("cp.async.wait_group 1;" ::: "memory");
        else             asm volatile("cp.async.wait_group 0;" ::: "memory");
        __syncthreads();

        uint32_t base = sb + (kc & 1) * GSTAGE;
#pragma unroll
        for (int k16 = 0; k16 < 32; k16 += 16) {
            uint32_t bh[4][2], bl[4][2];
#pragma unroll
            for (int bt = 0; bt < 2; bt++) {
                int nrow = wn0 + bt * 16 + (lane & 7) + ((lane >> 4) << 3);
                int kcol = k16 + ((lane >> 3) & 1) * 8;
                uint32_t ad = base + 2 * GTILE + nrow * (GST * 2) + kcol * 2;
                uint32_t r[4];
                ldmx4(r, ad);
                bh[bt * 2][0] = r[0]; bh[bt * 2][1] = r[1];
                bh[bt * 2 + 1][0] = r[2]; bh[bt * 2 + 1][1] = r[3];
                ldmx4(r, ad + GTILE);
                bl[bt * 2][0] = r[0]; bl[bt * 2][1] = r[1];
                bl[bt * 2 + 1][0] = r[2]; bl[bt * 2 + 1][1] = r[3];
            }
#pragma unroll
            for (int mt = 0; mt < 4; mt++) {
                int mrow = wm0 + mt * 16 + (lane & 15);
                int kcol = k16 + (lane >> 4) * 8;
                uint32_t ad = base + mrow * (GST * 2) + kcol * 2;
                uint32_t ah[4], al[4];
                ldmx4(ah, ad);
                ldmx4(al, ad + GTILE);
#pragma unroll
                for (int nt = 0; nt < 4; nt++) {
                    mma16816(acc[mt][nt], ah, bh[nt]);
                    mma16816(acc[mt][nt], ah, bl[nt]);
                    mma16816(acc[mt][nt], al, bh[nt]);
                }
            }
        }
        __syncthreads();
    }

    const int er = lane >> 2;
    const int ec = 2 * (lane & 3);
    if (Ch == nullptr) {
#pragma unroll
        for (int mt = 0; mt < 4; mt++)
#pragma unroll
            for (int nt = 0; nt < 4; nt++) {
                int r = m0 + wm0 + mt * 16 + er;
                int c = n0 + wn0 + nt * 8 + ec;
                *(float2*)(Cf + r * DMODEL + c) = make_float2(acc[mt][nt][0], acc[mt][nt][1]);
                *(float2*)(Cf + (r + 8) * DMODEL + c) = make_float2(acc[mt][nt][2], acc[mt][nt][3]);
            }
    } else {
#pragma unroll
        for (int mt = 0; mt < 4; mt++)
#pragma unroll
            for (int nt = 0; nt < 4; nt++) {
                int r = m0 + wm0 + mt * 16 + er;
                int c = n0 + wn0 + nt * 8 + ec;
                uint32_t h0, l0, h1, l1;
                pconv(acc[mt][nt][0], acc[mt][nt][1], h0, l0);
                pconv(acc[mt][nt][2], acc[mt][nt][3], h1, l1);
                *(uint32_t*)(Ch + r * DMODEL + c) = h0;
                *(uint32_t*)(Cl + r * DMODEL + c) = l0;
                *(uint32_t*)(Ch + (r + 8) * DMODEL + c) = h1;
                *(uint32_t*)(Cl + (r + 8) * DMODEL + c) = l1;
            }
    }
}

// ---------------------------------------------------------------------------
// Flash attention on mma.sync, causal, bf16x3 everywhere.
// CTA = 128 q-rows x 1 head, 256 threads / 8 warps (warp = 16 rows).
// Smem (dynamic 96KB): Qh[128x64]@0, Ql@16384,
//   stages@32768 + st*32768: Kh@0, Kl@8192, Vh@16384, Vl@24576.
// Layout: 16B-unit XOR swizzle addr = row*128 + ((unit ^ (row&7))<<4).
// ---------------------------------------------------------------------------
#define FSMEM 98304

__global__ __launch_bounds__(256, 1) void flash_mma_kernel(
    const __nv_bfloat16* __restrict__ Qh, const __nv_bfloat16* __restrict__ Ql,
    const __nv_bfloat16* __restrict__ Kh, const __nv_bfloat16* __restrict__ Kl,
    const __nv_bfloat16* __restrict__ Vh, const __nv_bfloat16* __restrict__ Vl,
    __nv_bfloat16* __restrict__ Oh, __nv_bfloat16* __restrict__ Ol)
{
    extern __shared__ char fsm[];
    const uint32_t sb = smem_u32(fsm);
    const int tid = threadIdx.x;
    const int lane = tid & 31, wid = tid >> 5;
    const int h = blockIdx.y;
    const int qt = gridDim.x - 1 - (int)blockIdx.x;   // long tiles first
    const int q0 = qt * 128;
    const int cb = h * DKH;
    const int nk = 2 * (qt + 1);
    const int wq = wid * 16;
    const int lr8 = lane & 7, lg = lane >> 3;

    // Initial loads: Q(h,l) + KV tile 0 in one commit group
#pragma unroll
    for (int i = 0; i < 4; i++) {
        int idx = i * 256 + tid;
        int r = idx >> 3, u = idx & 7;
        uint32_t so = r * 128 + ((u ^ (r & 7)) << 4);
        int go = (q0 + r) * DMODEL + cb + u * 8;
        cp16(sb + so, Qh + go);
        cp16(sb + 16384 + so, Ql + go);
    }
    {
        uint32_t base = sb + 32768;
#pragma unroll
        for (int i = 0; i < 2; i++) {
            int idx = i * 256 + tid;
            int r = idx >> 3, u = idx & 7;
            uint32_t so = r * 128 + ((u ^ (r & 7)) << 4);
            int go = r * DMODEL + cb + u * 8;
            cp16(base + so, Kh + go);
            cp16(base + 8192 + so, Kl + go);
            cp16(base + 16384 + so, Vh + go);
            cp16(base + 24576 + so, Vl + go);
        }
    }
    cp_commit();

    float m_lo = -1e30f, m_hi = -1e30f, l_lo = 0.f, l_hi = 0.f;
    float oacc[8][4];
#pragma unroll
    for (int t = 0; t < 8; t++)
#pragma unroll
        for (int e = 0; e < 4; e++) oacc[t][e] = 0.f;
    uint32_t qha[4][4], qla[4][4];

    for (int kt = 0; kt < nk; kt++) {
        if (kt + 1 < nk) {
            uint32_t base = sb + 32768 + ((kt + 1) & 1) * 32768;
            int s0 = (kt + 1) * 64;
#pragma unroll
            for (int i = 0; i < 2; i++) {
                int idx = i * 256 + tid;
                int r = idx >> 3, u = idx & 7;
                uint32_t so = r * 128 + ((u ^ (r & 7)) << 4);
                int go = (s0 + r) * DMODEL + cb + u * 8;
                cp16(base + so, Kh + go);
                cp16(base + 8192 + so, Kl + go);
                cp16(base + 16384 + so, Vh + go);
                cp16(base + 24576 + so, Vl + go);
            }
            cp_commit();
            asm volatile("cp.async.wait_group 1;" ::: "memory");
        } else {
            asm volatile("cp.async.wait_group 0;" ::: "memory");
        }
        __syncthreads();

        if (kt == 0) {
            // Q fragments (held in registers for the whole kernel)
#pragma unroll
            for (int ks = 0; ks < 4; ks++) {
                int qr = wq + (lg & 1) * 8 + lr8;
                int u = 2 * ks + (lg >> 1);
                uint32_t a = sb + qr * 128 + ((u ^ (qr & 7)) << 4);
                ldmx4(qha[ks], a);
                ldmx4(qla[ks], a + 16384);
            }
        }

        const uint32_t kvb = sb + 32768 + (kt & 1) * 32768;
        const bool skip = (kt * 64 > q0 + wq + 15);   // tile fully masked for this warp
        if (!skip) {
            // ---- S = Q K^T  (3-term bf16x3)
            float sacc[8][4];
#pragma unroll
            for (int t = 0; t < 8; t++)
#pragma unroll
                for (int e = 0; e < 4; e++) sacc[t][e] = 0.f;

#pragma unroll
            for (int ks = 0; ks < 4; ks++)
#pragma unroll
                for (int pj = 0; pj < 4; pj++) {
                    int kr = pj * 16 + (lg >> 1) * 8 + lr8;
                    int u = 2 * ks + (lg & 1);
                    uint32_t ka = kvb + kr * 128 + ((u ^ (kr & 7)) << 4);
                    uint32_t kh[4], kl[4];
                    ldmx4(kh, ka);
                    ldmx4(kl, ka + 8192);
                    mma16816(sacc[2 * pj], qha[ks], kh);
                    mma16816(sacc[2 * pj], qha[ks], kl);
                    mma16816(sacc[2 * pj], qla[ks], kh);
                    mma16816(sacc[2 * pj + 1], qha[ks], kh + 2);
                    mma16816(sacc[2 * pj + 1], qha[ks], kl + 2);
                    mma16816(sacc[2 * pj + 1], qla[ks], kh + 2);
                }

            // ---- scale + causal mask
            const int gr_lo = q0 + wq + (lane >> 2);
            const bool maskt = (kt * 64 + 63 > q0 + wq);
#pragma unroll
            for (int t = 0; t < 8; t++)
#pragma unroll
                for (int e = 0; e < 4; e++) {
                    float s = sacc[t][e] * 0.125f;
                    if (maskt) {
                        int col = kt * 64 + t * 8 + 2 * (lane & 3) + (e & 1);
                        int row = gr_lo + ((e >> 1) << 3);
                        if (col > row) s = -1e9f;
                    }
                    sacc[t][e] = s;
                }

            // ---- online softmax (rows split lo: e0,e1 / hi: e2,e3)
            float rx_lo = -1e30f, rx_hi = -1e30f;
#pragma unroll
            for (int t = 0; t < 8; t++) {
                rx_lo = fmaxf(rx_lo, fmaxf(sacc[t][0], sacc[t][1]));
                rx_hi = fmaxf(rx_hi, fmaxf(sacc[t][2], sacc[t][3]));
            }
            rx_lo = fmaxf(rx_lo, __shfl_xor_sync(0xffffffffu, rx_lo, 1));
            rx_lo = fmaxf(rx_lo, __shfl_xor_sync(0xffffffffu, rx_lo, 2));
            rx_hi = fmaxf(rx_hi, __shfl_xor_sync(0xffffffffu, rx_hi, 1));
            rx_hi = fmaxf(rx_hi, __shfl_xor_sync(0xffffffffu, rx_hi, 2));

            float mn_lo = fmaxf(m_lo, rx_lo);
            float mn_hi = fmaxf(m_hi, rx_hi);
            float al_lo = __expf(m_lo - mn_lo);
            float al_hi = __expf(m_hi - mn_hi);
            m_lo = mn_lo; m_hi = mn_hi;

            float sm_lo = 0.f, sm_hi = 0.f;
#pragma unroll
            for (int t = 0; t < 8; t++) {
                sacc[t][0] = __expf(sacc[t][0] - m_lo);
                sacc[t][1] = __expf(sacc[t][1] - m_lo);
                sacc[t][2] = __expf(sacc[t][2] - m_hi);
                sacc[t][3] = __expf(sacc[t][3] - m_hi);
                sm_lo += sacc[t][0] + sacc[t][1];
                sm_hi += sacc[t][2] + sacc[t][3];
            }
            sm_lo += __shfl_xor_sync(0xffffffffu, sm_lo, 1);
            sm_lo += __shfl_xor_sync(0xffffffffu, sm_lo, 2);
            sm_hi += __shfl_xor_sync(0xffffffffu, sm_hi, 1);
            sm_hi += __shfl_xor_sync(0xffffffffu, sm_hi, 2);
            l_lo = l_lo * al_lo + sm_lo;
            l_hi = l_hi * al_hi + sm_hi;
#pragma unroll
            for (int t = 0; t < 8; t++) {
                oacc[t][0] *= al_lo; oacc[t][1] *= al_lo;
                oacc[t][2] *= al_hi; oacc[t][3] *= al_hi;
            }

            // ---- P -> bf16 hi/lo A-fragments (register-only)
            uint32_t pha[4][4], pla[4][4];
#pragma unroll
            for (int ks = 0; ks < 4; ks++) {
                int t0 = 2 * ks, t1 = 2 * ks + 1;
                pconv(sacc[t0][0], sacc[t0][1], pha[ks][0], pla[ks][0]);
                pconv(sacc[t0][2], sacc[t0][3], pha[ks][1], pla[ks][1]);
                pconv(sacc[t1][0], sacc[t1][1], pha[ks][2], pla[ks][2]);
                pconv(sacc[t1][2], sacc[t1][3], pha[ks][3], pla[ks][3]);
            }

            // ---- O += P V  (3-term bf16x3, V via ldmatrix.trans)
#pragma unroll
            for (int ks = 0; ks < 4; ks++)
#pragma unroll
                for (int pj = 0; pj < 4; pj++) {
                    int vr = ks * 16 + (lg & 1) * 8 + lr8;
                    int u = 2 * pj + (lg >> 1);
                    uint32_t va = kvb + 16384 + vr * 128 + ((u ^ (vr & 7)) << 4);
                    uint32_t vh[4], vl[4];
                    ldmx4t(vh, va);
                    ldmx4t(vl, va + 8192);
                    mma16816(oacc[2 * pj], pha[ks], vh);
                    mma16816(oacc[2 * pj], pha[ks], vl);
                    mma16816(oacc[2 * pj], pla[ks], vh);
                    mma16816(oacc[2 * pj + 1], pha[ks], vh + 2);
                    mma16816(oacc[2 * pj + 1], pha[ks], vl + 2);
                    mma16816(oacc[2 * pj + 1], pla[ks], vh + 2);
                }
        }
        __syncthreads();   // all warps done with stage kt before it is overwritten
    }

    // ---- epilogue: normalize, split to bf16 hi/lo, store
    const float inv_lo = 1.0f / l_lo;
    const float inv_hi = 1.0f / l_hi;
    const int gr_lo = q0 + wq + (lane >> 2);
#pragma unroll
    for (int t = 0; t < 8; t++) {
        int c = cb + t * 8 + 2 * (lane & 3);
        {
            float o0 = oacc[t][0] * inv_lo, o1 = oacc[t][1] * inv_lo;
            uint32_t hh, ll;
            pconv(o0, o1, hh, ll);
            *(uint32_t*)(Oh + gr_lo * DMODEL + c) = hh;
            *(uint32_t*)(Ol + gr_lo * DMODEL + c) = ll;
        }
        {
            float o0 = oacc[t][2] * inv_hi, o1 = oacc[t][3] * inv_hi;
            uint32_t hh, ll;
            pconv(o0, o1, hh, ll);
            *(uint32_t*)(Oh + (gr_lo + 8) * DMODEL + c) = hh;
            *(uint32_t*)(Ol + (gr_lo + 8) * DMODEL + c) = ll;
        }
    }
}

// ---------------------------------------------------------------------------
extern "C" void kernel_launch(void* const* d_in, const int* in_sizes, int n_in,
                              void* d_out, int out_size)
{
    const float* Q  = (const float*)d_in[0];
    const float* K  = (const float*)d_in[1];
    const float* V  = (const float*)d_in[2];
    const float* WQ = (const float*)d_in[3];
    const float* WK = (const float*)d_in[4];
    const float* WV = (const float*)d_in[5];
    const float* WO = (const float*)d_in[6];
    float* out = (float*)d_out;

    __nv_bfloat16 *ah, *al, *bth, *btl;
    __nv_bfloat16 *qhh, *qhl, *khh, *khl, *vhh, *vhl, *ohh, *ohl;
    cudaGetSymbolAddress((void**)&ah, g_Ah);
    cudaGetSymbolAddress((void**)&al, g_Al);
    cudaGetSymbolAddress((void**)&bth, g_Bth);
    cudaGetSymbolAddress((void**)&btl, g_Btl);
    cudaGetSymbolAddress((void**)&qhh, g_Qhh);
    cudaGetSymbolAddress((void**)&qhl, g_Qhl);
    cudaGetSymbolAddress((void**)&khh, g_Khh);
    cudaGetSymbolAddress((void**)&khl, g_Khl);
    cudaGetSymbolAddress((void**)&vhh, g_Vhh);
    cudaGetSymbolAddress((void**)&vhl, g_Vhl);
    cudaGetSymbolAddress((void**)&ohh, g_Ohh);
    cudaGetSymbolAddress((void**)&ohl, g_Ohl);

    static bool attr_done = false;
    if (!attr_done) {
        cudaFuncSetAttribute(tc_gemm_kernel,
                             cudaFuncAttributeMaxDynamicSharedMemorySize, GSMEM);
        cudaFuncSetAttribute(flash_mma_kernel,
                             cudaFuncAttributeMaxDynamicSharedMemorySize, FSMEM);
        attr_done = true;
    }

    const int splitx_blocks = (SEQL * DMODEL / 4) / 256;
    const int splitw_blocks = (DMODEL * DMODEL) / 256;
    dim3 gg(DMODEL / 128, SEQL / 128);

    // Projections (epilogue writes bf16 hi/lo directly)
    split_x_kernel<<<splitx_blocks, 256>>>(Q, ah, al);
    split_w_kernel<<<splitw_blocks, 256>>>(WQ, bth, btl, 1);
    tc_gemm_kernel<<<gg, 256, GSMEM>>>(ah, al, bth, btl, nullptr, qhh, qhl);

    split_x_kernel<<<splitx_blocks, 256>>>(K, ah, al);
    split_w_kernel<<<splitw_blocks, 256>>>(WK, bth, btl, 1);
    tc_gemm_kernel<<<gg, 256, GSMEM>>>(ah, al, bth, btl, nullptr, khh, khl);

    split_x_kernel<<<splitx_blocks, 256>>>(V, ah, al);
    split_w_kernel<<<splitw_blocks, 256>>>(WV, bth, btl, 1);
    tc_gemm_kernel<<<gg, 256, GSMEM>>>(ah, al, bth, btl, nullptr, vhh, vhl);

    // Flash attention (writes bf16 hi/lo O)
    flash_mma_kernel<<<dim3(SEQL / 128, NH), 256, FSMEM>>>(
        qhh, qhl, khh, khl, vhh, vhl, ohh, ohl);

    // Output projection (fp32 out)
    split_w_kernel<<<splitw_blocks, 256>>>(WO, bth, btl, 0);
    tc_gemm_kernel<<<gg, 256, GSMEM>>>(ohh, ohl, bth, btl, out, nullptr, nullptr);
}

// round 6
// speedup vs baseline: 3.0639x; 1.0231x over previous
#include <cuda_runtime.h>
#include <cuda_bf16.h>
#include <cstdint>

#define SEQL 4096
#define DMODEL 1024
#define NH 16
#define DKH 64

// Scratch (allocation-free rule: static device globals)
static __device__ __nv_bfloat16 g_Ah[SEQL * DMODEL];
static __device__ __nv_bfloat16 g_Al[SEQL * DMODEL];
static __device__ __nv_bfloat16 g_Bth[DMODEL * DMODEL];
static __device__ __nv_bfloat16 g_Btl[DMODEL * DMODEL];
static __device__ __nv_bfloat16 g_Qhh[SEQL * DMODEL];
static __device__ __nv_bfloat16 g_Qhl[SEQL * DMODEL];
static __device__ __nv_bfloat16 g_Khh[SEQL * DMODEL];
static __device__ __nv_bfloat16 g_Khl[SEQL * DMODEL];
static __device__ __nv_bfloat16 g_Vhh[SEQL * DMODEL];
static __device__ __nv_bfloat16 g_Vhl[SEQL * DMODEL];
static __device__ __nv_bfloat16 g_Ohh[SEQL * DMODEL];
static __device__ __nv_bfloat16 g_Ohl[SEQL * DMODEL];

// ---------------- low-level helpers (base PTX only, no 'a' features) -------
__device__ __forceinline__ uint32_t smem_u32(const void* p) {
    uint32_t a;
    asm("{ .reg .u64 t; cvta.to.shared.u64 t, %1; cvt.u32.u64 %0, t; }" : "=r"(a) : "l"(p));
    return a;
}
__device__ __forceinline__ void cp16(uint32_t dst, const void* src) {
    asm volatile("cp.async.cg.shared.global [%0], [%1], 16;" :: "r"(dst), "l"(src));
}
__device__ __forceinline__ void cp_commit() {
    asm volatile("cp.async.commit_group;" ::: "memory");
}
__device__ __forceinline__ void ldmx4(uint32_t* r, uint32_t addr) {
    asm volatile("ldmatrix.sync.aligned.m8n8.x4.shared.b16 {%0,%1,%2,%3}, [%4];"
                 : "=r"(r[0]), "=r"(r[1]), "=r"(r[2]), "=r"(r[3]) : "r"(addr));
}
__device__ __forceinline__ void ldmx4t(uint32_t* r, uint32_t addr) {
    asm volatile("ldmatrix.sync.aligned.m8n8.x4.trans.shared.b16 {%0,%1,%2,%3}, [%4];"
                 : "=r"(r[0]), "=r"(r[1]), "=r"(r[2]), "=r"(r[3]) : "r"(addr));
}
__device__ __forceinline__ void mma16816(float* c, const uint32_t* a, const uint32_t* b) {
    asm volatile(
        "mma.sync.aligned.m16n8k16.row.col.f32.bf16.bf16.f32 "
        "{%0,%1,%2,%3}, {%4,%5,%6,%7}, {%8,%9}, {%0,%1,%2,%3};"
        : "+f"(c[0]), "+f"(c[1]), "+f"(c[2]), "+f"(c[3])
        : "r"(a[0]), "r"(a[1]), "r"(a[2]), "r"(a[3]), "r"(b[0]), "r"(b[1]));
}
// fp32 pair -> bf16 hi frag + bf16 residual frag (low half = first elem)
__device__ __forceinline__ void pconv(float s0, float s1, uint32_t& ph, uint32_t& pl) {
    __nv_bfloat162 h2 = __floats2bfloat162_rn(s0, s1);
    __nv_bfloat162 l2 = __floats2bfloat162_rn(s0 - __bfloat162float(h2.x),
                                              s1 - __bfloat162float(h2.y));
    ph = *(uint32_t*)&h2;
    pl = *(uint32_t*)&l2;
}

// ---------------------------------------------------------------------------
// Split fp32 -> bf16 hi/lo.
// ---------------------------------------------------------------------------
__global__ void split_x_kernel(const float* __restrict__ X,
                               __nv_bfloat16* __restrict__ H,
                               __nv_bfloat16* __restrict__ L)
{
    int i = (blockIdx.x * blockDim.x + threadIdx.x) * 4;
    float4 v = *(const float4*)(X + i);
    float vv[4] = {v.x, v.y, v.z, v.w};
    __nv_bfloat16 h[4], l[4];
#pragma unroll
    for (int j = 0; j < 4; j++) {
        h[j] = __float2bfloat16_rn(vv[j]);
        l[j] = __float2bfloat16_rn(vv[j] - __bfloat162float(h[j]));
    }
    *(__nv_bfloat162*)(H + i)     = __nv_bfloat162(h[0], h[1]);
    *(__nv_bfloat162*)(H + i + 2) = __nv_bfloat162(h[2], h[3]);
    *(__nv_bfloat162*)(L + i)     = __nv_bfloat162(l[0], l[1]);
    *(__nv_bfloat162*)(L + i + 2) = __nv_bfloat162(l[2], l[3]);
}

__global__ void split_w_kernel(const float* __restrict__ W,
                               __nv_bfloat16* __restrict__ H,
                               __nv_bfloat16* __restrict__ L, int blocked)
{
    int idx = blockIdx.x * blockDim.x + threadIdx.x;   // = n*1024 + k
    int n = idx >> 10, k = idx & 1023;
    float v = blocked ? W[(n >> 6) * (DMODEL * DKH) + k * DKH + (n & 63)]
                      : W[k * DMODEL + n];
    __nv_bfloat16 h = __float2bfloat16_rn(v);
    H[idx] = h;
    L[idx] = __float2bfloat16_rn(v - __bfloat162float(h));
}

// ---------------------------------------------------------------------------
// bf16x3 GEMM on mma.sync:  C = A @ Bt^T.  MMAs ordered term-major so each
// accumulator's revisit distance is >= 4 (hides HMMA latency).
// ---------------------------------------------------------------------------
#define GST 40
#define GTILE (128 * GST * 2)
#define GSTAGE (4 * GTILE)
#define GSMEM (2 * GSTAGE)

__global__ __launch_bounds__(256, 2) void tc_gemm_kernel(
    const __nv_bfloat16* __restrict__ Ah, const __nv_bfloat16* __restrict__ Al,
    const __nv_bfloat16* __restrict__ Bh, const __nv_bfloat16* __restrict__ Bl,
    float* __restrict__ Cf,
    __nv_bfloat16* __restrict__ Ch, __nv_bfloat16* __restrict__ Cl)
{
    extern __shared__ char smem[];
    const uint32_t sb = smem_u32(smem);
    const int tid = threadIdx.x;
    const int wid = tid >> 5, lane = tid & 31;
    const int m0 = blockIdx.y * 128;
    const int n0 = blockIdx.x * 128;
    const int wm0 = (wid & 1) * 64;
    const int wn0 = (wid >> 1) * 32;

    float acc[4][4][4];
#pragma unroll
    for (int i = 0; i < 4; i++)
#pragma unroll
        for (int j = 0; j < 4; j++)
#pragma unroll
            for (int t = 0; t < 4; t++) acc[i][j][t] = 0.f;

    const int lr = (2 * tid) >> 2;
    const int lc = (2 * tid) & 3;

    auto load_stage = [&](int st, int k0) {
        uint32_t base = sb + st * GSTAGE;
        const __nv_bfloat16* ga = Ah + (m0 + lr) * DMODEL + k0 + lc * 8;
        const __nv_bfloat16* gal = Al + (m0 + lr) * DMODEL + k0 + lc * 8;
        const __nv_bfloat16* gb = Bh + (n0 + lr) * DMODEL + k0 + lc * 8;
        const __nv_bfloat16* gbl = Bl + (n0 + lr) * DMODEL + k0 + lc * 8;
        uint32_t so = lr * (GST * 2) + lc * 16;
        cp16(base + so, ga);             cp16(base + so + 16, ga + 8);
        cp16(base + GTILE + so, gal);    cp16(base + GTILE + so + 16, gal + 8);
        cp16(base + 2 * GTILE + so, gb); cp16(base + 2 * GTILE + so + 16, gb + 8);
        cp16(base + 3 * GTILE + so, gbl);cp16(base + 3 * GTILE + so + 16, gbl + 8);
        cp_commit();
    };

    load_stage(0, 0);

    for (int kc = 0; kc < 32; kc++) {
        if (kc + 1 < 32) load_stage((kc + 1) & 1, (kc + 1) * 32);
        if (kc + 1 < 32) asm volatile("cp.async.wait_group 1;" ::: "memory");
        else             asm volatile("cp.async.wait_group 0;" ::: "memory");
        __syncthreads();

        uint32_t base = sb + (kc & 1) * GSTAGE;
#pragma unroll
        for (int k16 = 0; k16 < 32; k16 += 16) {
            uint32_t bh[4][2], bl[4][2];
#pragma unroll
            for (int bt = 0; bt < 2; bt++) {
                int nrow = wn0 + bt * 16 + (lane & 7) + ((lane >> 4) << 3);
                int kcol = k16 + ((lane >> 3) & 1) * 8;
                uint32_t ad = base + 2 * GTILE + nrow * (GST * 2) + kcol * 2;
                uint32_t r[4];
                ldmx4(r, ad);
                bh[bt * 2][0] = r[0]; bh[bt * 2][1] = r[1];
                bh[bt * 2 + 1][0] = r[2]; bh[bt * 2 + 1][1] = r[3];
                ldmx4(r, ad + GTILE);
                bl[bt * 2][0] = r[0]; bl[bt * 2][1] = r[1];
                bl[bt * 2 + 1][0] = r[2]; bl[bt * 2 + 1][1] = r[3];
            }
#pragma unroll
            for (int mt = 0; mt < 4; mt++) {
                int mrow = wm0 + mt * 16 + (lane & 15);
                int kcol = k16 + (lane >> 4) * 8;
                uint32_t ad = base + mrow * (GST * 2) + kcol * 2;
                uint32_t ah[4], al[4];
                ldmx4(ah, ad);
                ldmx4(al, ad + GTILE);
                // term-major: accumulator revisit distance = 4 MMAs
#pragma unroll
                for (int nt = 0; nt < 4; nt++) mma16816(acc[mt][nt], ah, bh[nt]);
#pragma unroll
                for (int nt = 0; nt < 4; nt++) mma16816(acc[mt][nt], ah, bl[nt]);
#pragma unroll
                for (int nt = 0; nt < 4; nt++) mma16816(acc[mt][nt], al, bh[nt]);
            }
        }
        __syncthreads();
    }

    const int er = lane >> 2;
    const int ec = 2 * (lane & 3);
    if (Ch == nullptr) {
#pragma unroll
        for (int mt = 0; mt < 4; mt++)
#pragma unroll
            for (int nt = 0; nt < 4; nt++) {
                int r = m0 + wm0 + mt * 16 + er;
                int c = n0 + wn0 + nt * 8 + ec;
                *(float2*)(Cf + r * DMODEL + c) = make_float2(acc[mt][nt][0], acc[mt][nt][1]);
                *(float2*)(Cf + (r + 8) * DMODEL + c) = make_float2(acc[mt][nt][2], acc[mt][nt][3]);
            }
    } else {
#pragma unroll
        for (int mt = 0; mt < 4; mt++)
#pragma unroll
            for (int nt = 0; nt < 4; nt++) {
                int r = m0 + wm0 + mt * 16 + er;
                int c = n0 + wn0 + nt * 8 + ec;
                uint32_t h0, l0, h1, l1;
                pconv(acc[mt][nt][0], acc[mt][nt][1], h0, l0);
                pconv(acc[mt][nt][2], acc[mt][nt][3], h1, l1);
                *(uint32_t*)(Ch + r * DMODEL + c) = h0;
                *(uint32_t*)(Cl + r * DMODEL + c) = l0;
                *(uint32_t*)(Ch + (r + 8) * DMODEL + c) = h1;
                *(uint32_t*)(Cl + (r + 8) * DMODEL + c) = l1;
            }
    }
}

// ---------------------------------------------------------------------------
// Flash attention on mma.sync, causal, bf16x3. MMAs ordered term-major
// (revisit distance 8) to break RAW chains on accumulators.
// ---------------------------------------------------------------------------
#define FSMEM 98304

__global__ __launch_bounds__(256, 1) void flash_mma_kernel(
    const __nv_bfloat16* __restrict__ Qh, const __nv_bfloat16* __restrict__ Ql,
    const __nv_bfloat16* __restrict__ Kh, const __nv_bfloat16* __restrict__ Kl,
    const __nv_bfloat16* __restrict__ Vh, const __nv_bfloat16* __restrict__ Vl,
    __nv_bfloat16* __restrict__ Oh, __nv_bfloat16* __restrict__ Ol)
{
    extern __shared__ char fsm[];
    const uint32_t sb = smem_u32(fsm);
    const int tid = threadIdx.x;
    const int lane = tid & 31, wid = tid >> 5;
    const int h = blockIdx.y;
    const int qt = gridDim.x - 1 - (int)blockIdx.x;   // long tiles first
    const int q0 = qt * 128;
    const int cb = h * DKH;
    const int nk = 2 * (qt + 1);
    const int wq = wid * 16;
    const int lr8 = lane & 7, lg = lane >> 3;

    // Initial loads: Q(h,l) + KV tile 0 in one commit group
#pragma unroll
    for (int i = 0; i < 4; i++) {
        int idx = i * 256 + tid;
        int r = idx >> 3, u = idx & 7;
        uint32_t so = r * 128 + ((u ^ (r & 7)) << 4);
        int go = (q0 + r) * DMODEL + cb + u * 8;
        cp16(sb + so, Qh + go);
        cp16(sb + 16384 + so, Ql + go);
    }
    {
        uint32_t base = sb + 32768;
#pragma unroll
        for (int i = 0; i < 2; i++) {
            int idx = i * 256 + tid;
            int r = idx >> 3, u = idx & 7;
            uint32_t so = r * 128 + ((u ^ (r & 7)) << 4);
            int go = r * DMODEL + cb + u * 8;
            cp16(base + so, Kh + go);
            cp16(base + 8192 + so, Kl + go);
            cp16(base + 16384 + so, Vh + go);
            cp16(base + 24576 + so, Vl + go);
        }
    }
    cp_commit();

    float m_lo = -1e30f, m_hi = -1e30f, l_lo = 0.f, l_hi = 0.f;
    float oacc[8][4];
#pragma unroll
    for (int t = 0; t < 8; t++)
#pragma unroll
        for (int e = 0; e < 4; e++) oacc[t][e] = 0.f;
    uint32_t qha[4][4], qla[4][4];

    for (int kt = 0; kt < nk; kt++) {
        if (kt + 1 < nk) {
            uint32_t base = sb + 32768 + ((kt + 1) & 1) * 32768;
            int s0 = (kt + 1) * 64;
#pragma unroll
            for (int i = 0; i < 2; i++) {
                int idx = i * 256 + tid;
                int r = idx >> 3, u = idx & 7;
                uint32_t so = r * 128 + ((u ^ (r & 7)) << 4);
                int go = (s0 + r) * DMODEL + cb + u * 8;
                cp16(base + so, Kh + go);
                cp16(base + 8192 + so, Kl + go);
                cp16(base + 16384 + so, Vh + go);
                cp16(base + 24576 + so, Vl + go);
            }
            cp_commit();
            asm volatile("cp.async.wait_group 1;" ::: "memory");
        } else {
            asm volatile("cp.async.wait_group 0;" ::: "memory");
        }
        __syncthreads();

        if (kt == 0) {
#pragma unroll
            for (int ks = 0; ks < 4; ks++) {
                int qr = wq + (lg & 1) * 8 + lr8;
                int u = 2 * ks + (lg >> 1);
                uint32_t a = sb + qr * 128 + ((u ^ (qr & 7)) << 4);
                ldmx4(qha[ks], a);
                ldmx4(qla[ks], a + 16384);
            }
        }

        const uint32_t kvb = sb + 32768 + (kt & 1) * 32768;
        const bool skip = (kt * 64 > q0 + wq + 15);
        if (!skip) {
            // ---- S = Q K^T  (3-term bf16x3, term-major issue order)
            float sacc[8][4];
#pragma unroll
            for (int t = 0; t < 8; t++)
#pragma unroll
                for (int e = 0; e < 4; e++) sacc[t][e] = 0.f;

#pragma unroll
            for (int ks = 0; ks < 4; ks++) {
                uint32_t kh[4][4], kl[4][4];
#pragma unroll
                for (int pj = 0; pj < 4; pj++) {
                    int kr = pj * 16 + (lg >> 1) * 8 + lr8;
                    int u = 2 * ks + (lg & 1);
                    uint32_t ka = kvb + kr * 128 + ((u ^ (kr & 7)) << 4);
                    ldmx4(kh[pj], ka);
                    ldmx4(kl[pj], ka + 8192);
                }
#pragma unroll
                for (int pj = 0; pj < 4; pj++) {
                    mma16816(sacc[2 * pj], qha[ks], kh[pj]);
                    mma16816(sacc[2 * pj + 1], qha[ks], kh[pj] + 2);
                }
#pragma unroll
                for (int pj = 0; pj < 4; pj++) {
                    mma16816(sacc[2 * pj], qha[ks], kl[pj]);
                    mma16816(sacc[2 * pj + 1], qha[ks], kl[pj] + 2);
                }
#pragma unroll
                for (int pj = 0; pj < 4; pj++) {
                    mma16816(sacc[2 * pj], qla[ks], kh[pj]);
                    mma16816(sacc[2 * pj + 1], qla[ks], kh[pj] + 2);
                }
            }

            // ---- scale + causal mask
            const int gr_lo = q0 + wq + (lane >> 2);
            const bool maskt = (kt * 64 + 63 > q0 + wq);
#pragma unroll
            for (int t = 0; t < 8; t++)
#pragma unroll
                for (int e = 0; e < 4; e++) {
                    float s = sacc[t][e] * 0.125f;
                    if (maskt) {
                        int col = kt * 64 + t * 8 + 2 * (lane & 3) + (e & 1);
                        int row = gr_lo + ((e >> 1) << 3);
                        if (col > row) s = -1e9f;
                    }
                    sacc[t][e] = s;
                }

            // ---- online softmax
            float rx_lo = -1e30f, rx_hi = -1e30f;
#pragma unroll
            for (int t = 0; t < 8; t++) {
                rx_lo = fmaxf(rx_lo, fmaxf(sacc[t][0], sacc[t][1]));
                rx_hi = fmaxf(rx_hi, fmaxf(sacc[t][2], sacc[t][3]));
            }
            rx_lo = fmaxf(rx_lo, __shfl_xor_sync(0xffffffffu, rx_lo, 1));
            rx_lo = fmaxf(rx_lo, __shfl_xor_sync(0xffffffffu, rx_lo, 2));
            rx_hi = fmaxf(rx_hi, __shfl_xor_sync(0xffffffffu, rx_hi, 1));
            rx_hi = fmaxf(rx_hi, __shfl_xor_sync(0xffffffffu, rx_hi, 2));

            float mn_lo = fmaxf(m_lo, rx_lo);
            float mn_hi = fmaxf(m_hi, rx_hi);
            float al_lo = __expf(m_lo - mn_lo);
            float al_hi = __expf(m_hi - mn_hi);
            m_lo = mn_lo; m_hi = mn_hi;

            float sm_lo = 0.f, sm_hi = 0.f;
#pragma unroll
            for (int t = 0; t < 8; t++) {
                sacc[t][0] = __expf(sacc[t][0] - m_lo);
                sacc[t][1] = __expf(sacc[t][1] - m_lo);
                sacc[t][2] = __expf(sacc[t][2] - m_hi);
                sacc[t][3] = __expf(sacc[t][3] - m_hi);
                sm_lo += sacc[t][0] + sacc[t][1];
                sm_hi += sacc[t][2] + sacc[t][3];
            }
            sm_lo += __shfl_xor_sync(0xffffffffu, sm_lo, 1);
            sm_lo += __shfl_xor_sync(0xffffffffu, sm_lo, 2);
            sm_hi += __shfl_xor_sync(0xffffffffu, sm_hi, 1);
            sm_hi += __shfl_xor_sync(0xffffffffu, sm_hi, 2);
            l_lo = l_lo * al_lo + sm_lo;
            l_hi = l_hi * al_hi + sm_hi;
#pragma unroll
            for (int t = 0; t < 8; t++) {
                oacc[t][0] *= al_lo; oacc[t][1] *= al_lo;
                oacc[t][2] *= al_hi; oacc[t][3] *= al_hi;
            }

            // ---- O += P V (per-ks convert, term-major issue order)
#pragma unroll
            for (int ks = 0; ks < 4; ks++) {
                uint32_t pha[4], pla[4];
                int t0 = 2 * ks, t1 = 2 * ks + 1;
                pconv(sacc[t0][0], sacc[t0][1], pha[0], pla[0]);
                pconv(sacc[t0][2], sacc[t0][3], pha[1], pla[1]);
                pconv(sacc[t1][0], sacc[t1][1], pha[2], pla[2]);
                pconv(sacc[t1][2], sacc[t1][3], pha[3], pla[3]);

                uint32_t vh[4][4], vl[4][4];
#pragma unroll
                for (int pj = 0; pj < 4; pj++) {
                    int vr = ks * 16 + (lg & 1) * 8 + lr8;
                    int u = 2 * pj + (lg >> 1);
                    uint32_t va = kvb + 16384 + vr * 128 + ((u ^ (vr & 7)) << 4);
                    ldmx4t(vh[pj], va);
                    ldmx4t(vl[pj], va + 8192);
                }
#pragma unroll
                for (int pj = 0; pj < 4; pj++) {
                    mma16816(oacc[2 * pj], pha, vh[pj]);
                    mma16816(oacc[2 * pj + 1], pha, vh[pj] + 2);
                }
#pragma unroll
                for (int pj = 0; pj < 4; pj++) {
                    mma16816(oacc[2 * pj], pha, vl[pj]);
                    mma16816(oacc[2 * pj + 1], pha, vl[pj] + 2);
                }
#pragma unroll
                for (int pj = 0; pj < 4; pj++) {
                    mma16816(oacc[2 * pj], pla, vh[pj]);
                    mma16816(oacc[2 * pj + 1], pla, vh[pj] + 2);
                }
            }
        }
        __syncthreads();
    }

    // ---- epilogue
    const float inv_lo = 1.0f / l_lo;
    const float inv_hi = 1.0f / l_hi;
    const int gr_lo = q0 + wq + (lane >> 2);
#pragma unroll
    for (int t = 0; t < 8; t++) {
        int c = cb + t * 8 + 2 * (lane & 3);
        {
            float o0 = oacc[t][0] * inv_lo, o1 = oacc[t][1] * inv_lo;
            uint32_t hh, ll;
            pconv(o0, o1, hh, ll);
            *(uint32_t*)(Oh + gr_lo * DMODEL + c) = hh;
            *(uint32_t*)(Ol + gr_lo * DMODEL + c) = ll;
        }
        {
            float o0 = oacc[t][2] * inv_hi, o1 = oacc[t][3] * inv_hi;
            uint32_t hh, ll;
            pconv(o0, o1, hh, ll);
            *(uint32_t*)(Oh + (gr_lo + 8) * DMODEL + c) = hh;
            *(uint32_t*)(Ol + (gr_lo + 8) * DMODEL + c) = ll;
        }
    }
}

// ---------------------------------------------------------------------------
extern "C" void kernel_launch(void* const* d_in, const int* in_sizes, int n_in,
                              void* d_out, int out_size)
{
    const float* Q  = (const float*)d_in[0];
    const float* K  = (const float*)d_in[1];
    const float* V  = (const float*)d_in[2];
    const float* WQ = (const float*)d_in[3];
    const float* WK = (const float*)d_in[4];
    const float* WV = (const float*)d_in[5];
    const float* WO = (const float*)d_in[6];
    float* out = (float*)d_out;

    __nv_bfloat16 *ah, *al, *bth, *btl;
    __nv_bfloat16 *qhh, *qhl, *khh, *khl, *vhh, *vhl, *ohh, *ohl;
    cudaGetSymbolAddress((void**)&ah, g_Ah);
    cudaGetSymbolAddress((void**)&al, g_Al);
    cudaGetSymbolAddress((void**)&bth, g_Bth);
    cudaGetSymbolAddress((void**)&btl, g_Btl);
    cudaGetSymbolAddress((void**)&qhh, g_Qhh);
    cudaGetSymbolAddress((void**)&qhl, g_Qhl);
    cudaGetSymbolAddress((void**)&khh, g_Khh);
    cudaGetSymbolAddress((void**)&khl, g_Khl);
    cudaGetSymbolAddress((void**)&vhh, g_Vhh);
    cudaGetSymbolAddress((void**)&vhl, g_Vhl);
    cudaGetSymbolAddress((void**)&ohh, g_Ohh);
    cudaGetSymbolAddress((void**)&ohl, g_Ohl);

    static bool attr_done = false;
    if (!attr_done) {
        cudaFuncSetAttribute(tc_gemm_kernel,
                             cudaFuncAttributeMaxDynamicSharedMemorySize, GSMEM);
        cudaFuncSetAttribute(flash_mma_kernel,
                             cudaFuncAttributeMaxDynamicSharedMemorySize, FSMEM);
        attr_done = true;
    }

    const int splitx_blocks = (SEQL * DMODEL / 4) / 256;
    const int splitw_blocks = (DMODEL * DMODEL) / 256;
    dim3 gg(DMODEL / 128, SEQL / 128);

    split_x_kernel<<<splitx_blocks, 256>>>(Q, ah, al);
    split_w_kernel<<<splitw_blocks, 256>>>(WQ, bth, btl, 1);
    tc_gemm_kernel<<<gg, 256, GSMEM>>>(ah, al, bth, btl, nullptr, qhh, qhl);

    split_x_kernel<<<splitx_blocks, 256>>>(K, ah, al);
    split_w_kernel<<<splitw_blocks, 256>>>(WK, bth, btl, 1);
    tc_gemm_kernel<<<gg, 256, GSMEM>>>(ah, al, bth, btl, nullptr, khh, khl);

    split_x_kernel<<<splitx_blocks, 256>>>(V, ah, al);
    split_w_kernel<<<splitw_blocks, 256>>>(WV, bth, btl, 1);
    tc_gemm_kernel<<<gg, 256, GSMEM>>>(ah, al, bth, btl, nullptr, vhh, vhl);

    flash_mma_kernel<<<dim3(SEQL / 128, NH), 256, FSMEM>>>(
        qhh, qhl, khh, khl, vhh, vhl, ohh, ohl);

    split_w_kernel<<<splitw_blocks, 256>>>(WO, bth, btl, 0);
    tc_gemm_kernel<<<gg, 256, GSMEM>>>(ohh, ohl, bth, btl, out, nullptr, nullptr);
}

// round 8
// speedup vs baseline: 3.0889x; 1.0082x over previous
#include <cuda_runtime.h>
#include <cuda_bf16.h>
#include <cstdint>

#define SEQL 4096
#define DMODEL 1024
#define NH 16
#define DKH 64

// Scratch (allocation-free rule: static device globals)
static __device__ __nv_bfloat16 g_Qih[SEQL * DMODEL], g_Qil[SEQL * DMODEL];
static __device__ __nv_bfloat16 g_Kih[SEQL * DMODEL], g_Kil[SEQL * DMODEL];
static __device__ __nv_bfloat16 g_Vih[SEQL * DMODEL], g_Vil[SEQL * DMODEL];
static __device__ __nv_bfloat16 g_Wqh[DMODEL * DMODEL], g_Wql[DMODEL * DMODEL];
static __device__ __nv_bfloat16 g_Wkh[DMODEL * DMODEL], g_Wkl[DMODEL * DMODEL];
static __device__ __nv_bfloat16 g_Wvh[DMODEL * DMODEL], g_Wvl[DMODEL * DMODEL];
static __device__ __nv_bfloat16 g_Woh[DMODEL * DMODEL], g_Wol[DMODEL * DMODEL];
static __device__ __nv_bfloat16 g_Qhh[SEQL * DMODEL], g_Qhl[SEQL * DMODEL];
static __device__ __nv_bfloat16 g_Khh[SEQL * DMODEL], g_Khl[SEQL * DMODEL];
static __device__ __nv_bfloat16 g_Vhh[SEQL * DMODEL], g_Vhl[SEQL * DMODEL];
static __device__ __nv_bfloat16 g_Ohh[SEQL * DMODEL], g_Ohl[SEQL * DMODEL];

// ---------------- low-level helpers (base PTX only, no 'a' features) -------
__device__ __forceinline__ uint32_t smem_u32(const void* p) {
    uint32_t a;
    asm("{ .reg .u64 t; cvta.to.shared.u64 t, %1; cvt.u32.u64 %0, t; }" : "=r"(a) : "l"(p));
    return a;
}
__device__ __forceinline__ void cp16(uint32_t dst, const void* src) {
    asm volatile("cp.async.cg.shared.global [%0], [%1], 16;" :: "r"(dst), "l"(src));
}
__device__ __forceinline__ void cp_commit() {
    asm volatile("cp.async.commit_group;" ::: "memory");
}
__device__ __forceinline__ void ldmx4(uint32_t* r, uint32_t addr) {
    asm volatile("ldmatrix.sync.aligned.m8n8.x4.shared.b16 {%0,%1,%2,%3}, [%4];"
                 : "=r"(r[0]), "=r"(r[1]), "=r"(r[2]), "=r"(r[3]) : "r"(addr));
}
__device__ __forceinline__ void ldmx4t(uint32_t* r, uint32_t addr) {
    asm volatile("ldmatrix.sync.aligned.m8n8.x4.trans.shared.b16 {%0,%1,%2,%3}, [%4];"
                 : "=r"(r[0]), "=r"(r[1]), "=r"(r[2]), "=r"(r[3]) : "r"(addr));
}
__device__ __forceinline__ void mma16816(float* c, const uint32_t* a, const uint32_t* b) {
    asm volatile(
        "mma.sync.aligned.m16n8k16.row.col.f32.bf16.bf16.f32 "
        "{%0,%1,%2,%3}, {%4,%5,%6,%7}, {%8,%9}, {%0,%1,%2,%3};"
        : "+f"(c[0]), "+f"(c[1]), "+f"(c[2]), "+f"(c[3])
        : "r"(a[0]), "r"(a[1]), "r"(a[2]), "r"(a[3]), "r"(b[0]), "r"(b[1]));
}
__device__ __forceinline__ void pconv(float s0, float s1, uint32_t& ph, uint32_t& pl) {
    __nv_bfloat162 h2 = __floats2bfloat162_rn(s0, s1);
    __nv_bfloat162 l2 = __floats2bfloat162_rn(s0 - __bfloat162float(h2.x),
                                              s1 - __bfloat162float(h2.y));
    ph = *(uint32_t*)&h2;
    pl = *(uint32_t*)&l2;
}

// ---------------------------------------------------------------------------
// Split all three inputs (z selects Q/K/V) fp32 -> bf16 hi/lo.
// ---------------------------------------------------------------------------
__global__ void split_inputs_kernel(
    const float* __restrict__ Q, const float* __restrict__ K,
    const float* __restrict__ V,
    __nv_bfloat16* __restrict__ Qh, __nv_bfloat16* __restrict__ Ql,
    __nv_bfloat16* __restrict__ Kh, __nv_bfloat16* __restrict__ Kl,
    __nv_bfloat16* __restrict__ Vh, __nv_bfloat16* __restrict__ Vl)
{
    const int z = blockIdx.z;
    const float* X = (z == 0) ? Q : (z == 1) ? K : V;
    __nv_bfloat16* H = (z == 0) ? Qh : (z == 1) ? Kh : Vh;
    __nv_bfloat16* L = (z == 0) ? Ql : (z == 1) ? Kl : Vl;
    int i = (blockIdx.x * blockDim.x + threadIdx.x) * 4;
    float4 v = *(const float4*)(X + i);
    float vv[4] = {v.x, v.y, v.z, v.w};
    __nv_bfloat16 h[4], l[4];
#pragma unroll
    for (int j = 0; j < 4; j++) {
        h[j] = __float2bfloat16_rn(vv[j]);
        l[j] = __float2bfloat16_rn(vv[j] - __bfloat162float(h[j]));
    }
    *(__nv_bfloat162*)(H + i)     = __nv_bfloat162(h[0], h[1]);
    *(__nv_bfloat162*)(H + i + 2) = __nv_bfloat162(h[2], h[3]);
    *(__nv_bfloat162*)(L + i)     = __nv_bfloat162(l[0], l[1]);
    *(__nv_bfloat162*)(L + i + 2) = __nv_bfloat162(l[2], l[3]);
}

// ---------------------------------------------------------------------------
// Split all four weights (z selects WQ/WK/WV/WO) -> Bt[n][k] bf16 hi/lo.
// ---------------------------------------------------------------------------
__global__ void split_weights_kernel(
    const float* __restrict__ WQ, const float* __restrict__ WK,
    const float* __restrict__ WV, const float* __restrict__ WO,
    __nv_bfloat16* __restrict__ Qh, __nv_bfloat16* __restrict__ Ql,
    __nv_bfloat16* __restrict__ Kh, __nv_bfloat16* __restrict__ Kl,
    __nv_bfloat16* __restrict__ Vh, __nv_bfloat16* __restrict__ Vl,
    __nv_bfloat16* __restrict__ Oh, __nv_bfloat16* __restrict__ Ol)
{
    const int z = blockIdx.z;
    const float* W = (z == 0) ? WQ : (z == 1) ? WK : (z == 2) ? WV : WO;
    __nv_bfloat16* H = (z == 0) ? Qh : (z == 1) ? Kh : (z == 2) ? Vh : Oh;
    __nv_bfloat16* L = (z == 0) ? Ql : (z == 1) ? Kl : (z == 2) ? Vl : Ol;
    int idx = blockIdx.x * blockDim.x + threadIdx.x;   // = n*1024 + k
    int n = idx >> 10, k = idx & 1023;
    float v = (z < 3) ? W[(n >> 6) * (DMODEL * DKH) + k * DKH + (n & 63)]
                      : W[k * DMODEL + n];
    __nv_bfloat16 h = __float2bfloat16_rn(v);
    H[idx] = h;
    L[idx] = __float2bfloat16_rn(v - __bfloat162float(h));
}

// ---------------------------------------------------------------------------
// bf16x3 GEMM on mma.sync:  C = A @ Bt^T (term-major issue order).
// ---------------------------------------------------------------------------
#define GST 40
#define GTILE (128 * GST * 2)
#define GSTAGE (4 * GTILE)
#define GSMEM (2 * GSTAGE)

__global__ __launch_bounds__(256, 2) void tc_gemm_kernel(
    const __nv_bfloat16* __restrict__ Ah, const __nv_bfloat16* __restrict__ Al,
    const __nv_bfloat16* __restrict__ Bh, const __nv_bfloat16* __restrict__ Bl,
    float* __restrict__ Cf,
    __nv_bfloat16* __restrict__ Ch, __nv_bfloat16* __restrict__ Cl)
{
    extern __shared__ char smem[];
    const uint32_t sb = smem_u32(smem);
    const int tid = threadIdx.x;
    const int wid = tid >> 5, lane = tid & 31;
    const int m0 = blockIdx.y * 128;
    const int n0 = blockIdx.x * 128;
    const int wm0 = (wid & 1) * 64;
    const int wn0 = (wid >> 1) * 32;

    float acc[4][4][4];
#pragma unroll
    for (int i = 0; i < 4; i++)
#pragma unroll
        for (int j = 0; j < 4; j++)
#pragma unroll
            for (int t = 0; t < 4; t++) acc[i][j][t] = 0.f;

    const int lr = (2 * tid) >> 2;
    const int lc = (2 * tid) & 3;

    auto load_stage = [&](int st, int k0) {
        uint32_t base = sb + st * GSTAGE;
        const __nv_bfloat16* ga = Ah + (m0 + lr) * DMODEL + k0 + lc * 8;
        const __nv_bfloat16* gal = Al + (m0 + lr) * DMODEL + k0 + lc * 8;
        const __nv_bfloat16* gb = Bh + (n0 + lr) * DMODEL + k0 + lc * 8;
        const __nv_bfloat16* gbl = Bl + (n0 + lr) * DMODEL + k0 + lc * 8;
        uint32_t so = lr * (GST * 2) + lc * 16;
        cp16(base + so, ga);             cp16(base + so + 16, ga + 8);
        cp16(base + GTILE + so, gal);    cp16(base + GTILE + so + 16, gal + 8);
        cp16(base + 2 * GTILE + so, gb); cp16(base + 2 * GTILE + so + 16, gb + 8);
        cp16(base + 3 * GTILE + so, gbl);cp16(base + 3 * GTILE + so + 16, gbl + 8);
        cp_commit();
    };

    load_stage(0, 0);

    for (int kc = 0; kc < 32; kc++) {
        if (kc + 1 < 32) load_stage((kc + 1) & 1, (kc + 1) * 32);
        if (kc + 1 < 32) asm volatile("cp.async.wait_group 1;" ::: "memory");
        else             asm volatile("cp.async.wait_group 0;" ::: "memory");
        __syncthreads();

        uint32_t base = sb + (kc & 1) * GSTAGE;
#pragma unroll
        for (int k16 = 0; k16 < 32; k16 += 16) {
            uint32_t bh[4][2], bl[4][2];
#pragma unroll
            for (int bt = 0; bt < 2; bt++) {
                int nrow = wn0 + bt * 16 + (lane & 7) + ((lane >> 4) << 3);
                int kcol = k16 + ((lane >> 3) & 1) * 8;
                uint32_t ad = base + 2 * GTILE + nrow * (GST * 2) + kcol * 2;
                uint32_t r[4];
                ldmx4(r, ad);
                bh[bt * 2][0] = r[0]; bh[bt * 2][1] = r[1];
                bh[bt * 2 + 1][0] = r[2]; bh[bt * 2 + 1][1] = r[3];
                ldmx4(r, ad + GTILE);
                bl[bt * 2][0] = r[0]; bl[bt * 2][1] = r[1];
                bl[bt * 2 + 1][0] = r[2]; bl[bt * 2 + 1][1] = r[3];
            }
#pragma unroll
            for (int mt = 0; mt < 4; mt++) {
                int mrow = wm0 + mt * 16 + (lane & 15);
                int kcol = k16 + (lane >> 4) * 8;
                uint32_t ad = base + mrow * (GST * 2) + kcol * 2;
                uint32_t ah[4], al[4];
                ldmx4(ah, ad);
                ldmx4(al, ad + GTILE);
#pragma unroll
                for (int nt = 0; nt < 4; nt++) mma16816(acc[mt][nt], ah, bh[nt]);
#pragma unroll
                for (int nt = 0; nt < 4; nt++) mma16816(acc[mt][nt], ah, bl[nt]);
#pragma unroll
                for (int nt = 0; nt < 4; nt++) mma16816(acc[mt][nt], al, bh[nt]);
            }
        }
        __syncthreads();
    }

    const int er = lane >> 2;
    const int ec = 2 * (lane & 3);
    if (Ch == nullptr) {
#pragma unroll
        for (int mt = 0; mt < 4; mt++)
#pragma unroll
            for (int nt = 0; nt < 4; nt++) {
                int r = m0 + wm0 + mt * 16 + er;
                int c = n0 + wn0 + nt * 8 + ec;
                *(float2*)(Cf + r * DMODEL + c) = make_float2(acc[mt][nt][0], acc[mt][nt][1]);
                *(float2*)(Cf + (r + 8) * DMODEL + c) = make_float2(acc[mt][nt][2], acc[mt][nt][3]);
            }
    } else {
#pragma unroll
        for (int mt = 0; mt < 4; mt++)
#pragma unroll
            for (int nt = 0; nt < 4; nt++) {
                int r = m0 + wm0 + mt * 16 + er;
                int c = n0 + wn0 + nt * 8 + ec;
                uint32_t h0, l0, h1, l1;
                pconv(acc[mt][nt][0], acc[mt][nt][1], h0, l0);
                pconv(acc[mt][nt][2], acc[mt][nt][3], h1, l1);
                *(uint32_t*)(Ch + r * DMODEL + c) = h0;
                *(uint32_t*)(Cl + r * DMODEL + c) = l0;
                *(uint32_t*)(Ch + (r + 8) * DMODEL + c) = h1;
                *(uint32_t*)(Cl + (r + 8) * DMODEL + c) = l1;
            }
    }
}

// ---------------------------------------------------------------------------
// Flash attention on mma.sync, causal, bf16x3. 3-stage KV pipeline,
// prefetch distance 2. ONE barrier per iteration, placed AFTER the
// wait_group (cp.async completion is per-thread: the barrier makes all
// threads' stage-kt copies visible before any ldmatrix reads them) and
// BEFORE the next cp-issue (so stage (kt+2)%3 is not rewritten while
// iteration kt-1 readers are still on it).
// Group accounting: stage s <-> commit group s; wait_group 1 at top of
// iteration kt guarantees stage kt landed.
// ---------------------------------------------------------------------------
#define FSMEM 131072

__global__ __launch_bounds__(256, 1) void flash_mma_kernel(
    const __nv_bfloat16* __restrict__ Qh, const __nv_bfloat16* __restrict__ Ql,
    const __nv_bfloat16* __restrict__ Kh, const __nv_bfloat16* __restrict__ Kl,
    const __nv_bfloat16* __restrict__ Vh, const __nv_bfloat16* __restrict__ Vl,
    __nv_bfloat16* __restrict__ Oh, __nv_bfloat16* __restrict__ Ol)
{
    extern __shared__ char fsm[];
    const uint32_t sb = smem_u32(fsm);
    const int tid = threadIdx.x;
    const int lane = tid & 31, wid = tid >> 5;
    const int h = blockIdx.y;
    const int qt = gridDim.x - 1 - (int)blockIdx.x;   // long tiles first
    const int q0 = qt * 128;
    const int cb = h * DKH;
    const int nk = 2 * (qt + 1);
    const int wq = wid * 16;
    const int lr8 = lane & 7, lg = lane >> 3;

    auto load_kv = [&](int stage, int s0) {
        uint32_t base = sb + 32768 + stage * 32768;
#pragma unroll
        for (int i = 0; i < 2; i++) {
            int idx = i * 256 + tid;
            int r = idx >> 3, u = idx & 7;
            uint32_t so = r * 128 + ((u ^ (r & 7)) << 4);
            int go = (s0 + r) * DMODEL + cb + u * 8;
            cp16(base + so, Kh + go);
            cp16(base + 8192 + so, Kl + go);
            cp16(base + 16384 + so, Vh + go);
            cp16(base + 24576 + so, Vl + go);
        }
    };

    // group 0: Q(h,l) + KV stage 0
#pragma unroll
    for (int i = 0; i < 4; i++) {
        int idx = i * 256 + tid;
        int r = idx >> 3, u = idx & 7;
        uint32_t so = r * 128 + ((u ^ (r & 7)) << 4);
        int go = (q0 + r) * DMODEL + cb + u * 8;
        cp16(sb + so, Qh + go);
        cp16(sb + 16384 + so, Ql + go);
    }
    load_kv(0, 0);
    cp_commit();
    // group 1: KV stage 1 (empty group when nk == 1)
    if (nk > 1) load_kv(1, 64);
    cp_commit();

    float m_lo = -1e30f, m_hi = -1e30f, l_lo = 0.f, l_hi = 0.f;
    float oacc[8][4];
#pragma unroll
    for (int t = 0; t < 8; t++)
#pragma unroll
        for (int e = 0; e < 4; e++) oacc[t][e] = 0.f;
    uint32_t qha[4][4], qla[4][4];

    for (int kt = 0; kt < nk; kt++) {
        // stage kt == group kt; at most group kt+1 left pending
        asm volatile("cp.async.wait_group 1;" ::: "memory");
        __syncthreads();   // all threads' stage-kt copies visible; prior reads done
        if (kt + 2 < nk) load_kv((kt + 2) % 3, (kt + 2) * 64);
        cp_commit();       // exactly one group per iteration (group kt+2)

        if (kt == 0) {
#pragma unroll
            for (int ks = 0; ks < 4; ks++) {
                int qr = wq + (lg & 1) * 8 + lr8;
                int u = 2 * ks + (lg >> 1);
                uint32_t a = sb + qr * 128 + ((u ^ (qr & 7)) << 4);
                ldmx4(qha[ks], a);
                ldmx4(qla[ks], a + 16384);
            }
        }

        const uint32_t kvb = sb + 32768 + (kt % 3) * 32768;
        const bool skip = (kt * 64 > q0 + wq + 15);
        if (!skip) {
            // ---- S = Q K^T
            float sacc[8][4];
#pragma unroll
            for (int t = 0; t < 8; t++)
#pragma unroll
                for (int e = 0; e < 4; e++) sacc[t][e] = 0.f;

#pragma unroll
            for (int ks = 0; ks < 4; ks++) {
                uint32_t kh[4][4], kl[4][4];
#pragma unroll
                for (int pj = 0; pj < 4; pj++) {
                    int kr = pj * 16 + (lg >> 1) * 8 + lr8;
                    int u = 2 * ks + (lg & 1);
                    uint32_t ka = kvb + kr * 128 + ((u ^ (kr & 7)) << 4);
                    ldmx4(kh[pj], ka);
                    ldmx4(kl[pj], ka + 8192);
                }
#pragma unroll
                for (int pj = 0; pj < 4; pj++) {
                    mma16816(sacc[2 * pj], qha[ks], kh[pj]);
                    mma16816(sacc[2 * pj + 1], qha[ks], kh[pj] + 2);
                }
#pragma unroll
                for (int pj = 0; pj < 4; pj++) {
                    mma16816(sacc[2 * pj], qha[ks], kl[pj]);
                    mma16816(sacc[2 * pj + 1], qha[ks], kl[pj] + 2);
                }
#pragma unroll
                for (int pj = 0; pj < 4; pj++) {
                    mma16816(sacc[2 * pj], qla[ks], kh[pj]);
                    mma16816(sacc[2 * pj + 1], qla[ks], kh[pj] + 2);
                }
            }

            // ---- scale + causal mask
            const int gr_lo = q0 + wq + (lane >> 2);
            const bool maskt = (kt * 64 + 63 > q0 + wq);
#pragma unroll
            for (int t = 0; t < 8; t++)
#pragma unroll
                for (int e = 0; e < 4; e++) {
                    float s = sacc[t][e] * 0.125f;
                    if (maskt) {
                        int col = kt * 64 + t * 8 + 2 * (lane & 3) + (e & 1);
                        int row = gr_lo + ((e >> 1) << 3);
                        if (col > row) s = -1e9f;
                    }
                    sacc[t][e] = s;
                }

            // ---- online softmax
            float rx_lo = -1e30f, rx_hi = -1e30f;
#pragma unroll
            for (int t = 0; t < 8; t++) {
                rx_lo = fmaxf(rx_lo, fmaxf(sacc[t][0], sacc[t][1]));
                rx_hi = fmaxf(rx_hi, fmaxf(sacc[t][2], sacc[t][3]));
            }
            rx_lo = fmaxf(rx_lo, __shfl_xor_sync(0xffffffffu, rx_lo, 1));
            rx_lo = fmaxf(rx_lo, __shfl_xor_sync(0xffffffffu, rx_lo, 2));
            rx_hi = fmaxf(rx_hi, __shfl_xor_sync(0xffffffffu, rx_hi, 1));
            rx_hi = fmaxf(rx_hi, __shfl_xor_sync(0xffffffffu, rx_hi, 2));

            float mn_lo = fmaxf(m_lo, rx_lo);
            float mn_hi = fmaxf(m_hi, rx_hi);
            float al_lo = __expf(m_lo - mn_lo);
            float al_hi = __expf(m_hi - mn_hi);
            m_lo = mn_lo; m_hi = mn_hi;

            float sm_lo = 0.f, sm_hi = 0.f;
#pragma unroll
            for (int t = 0; t < 8; t++) {
                sacc[t][0] = __expf(sacc[t][0] - m_lo);
                sacc[t][1] = __expf(sacc[t][1] - m_lo);
                sacc[t][2] = __expf(sacc[t][2] - m_hi);
                sacc[t][3] = __expf(sacc[t][3] - m_hi);
                sm_lo += sacc[t][0] + sacc[t][1];
                sm_hi += sacc[t][2] + sacc[t][3];
            }
            sm_lo += __shfl_xor_sync(0xffffffffu, sm_lo, 1);
            sm_lo += __shfl_xor_sync(0xffffffffu, sm_lo, 2);
            sm_hi += __shfl_xor_sync(0xffffffffu, sm_hi, 1);
            sm_hi += __shfl_xor_sync(0xffffffffu, sm_hi, 2);
            l_lo = l_lo * al_lo + sm_lo;
            l_hi = l_hi * al_hi + sm_hi;
#pragma unroll
            for (int t = 0; t < 8; t++) {
                oacc[t][0] *= al_lo; oacc[t][1] *= al_lo;
                oacc[t][2] *= al_hi; oacc[t][3] *= al_hi;
            }

            // ---- O += P V
#pragma unroll
            for (int ks = 0; ks < 4; ks++) {
                uint32_t pha[4], pla[4];
                int t0 = 2 * ks, t1 = 2 * ks + 1;
                pconv(sacc[t0][0], sacc[t0][1], pha[0], pla[0]);
                pconv(sacc[t0][2], sacc[t0][3], pha[1], pla[1]);
                pconv(sacc[t1][0], sacc[t1][1], pha[2], pla[2]);
                pconv(sacc[t1][2], sacc[t1][3], pha[3], pla[3]);

                uint32_t vh[4][4], vl[4][4];
#pragma unroll
                for (int pj = 0; pj < 4; pj++) {
                    int vr = ks * 16 + (lg & 1) * 8 + lr8;
                    int u = 2 * pj + (lg >> 1);
                    uint32_t va = kvb + 16384 + vr * 128 + ((u ^ (vr & 7)) << 4);
                    ldmx4t(vh[pj], va);
                    ldmx4t(vl[pj], va + 8192);
                }
#pragma unroll
                for (int pj = 0; pj < 4; pj++) {
                    mma16816(oacc[2 * pj], pha, vh[pj]);
                    mma16816(oacc[2 * pj + 1], pha, vh[pj] + 2);
                }
#pragma unroll
                for (int pj = 0; pj < 4; pj++) {
                    mma16816(oacc[2 * pj], pha, vl[pj]);
                    mma16816(oacc[2 * pj + 1], pha, vl[pj] + 2);
                }
#pragma unroll
                for (int pj = 0; pj < 4; pj++) {
                    mma16816(oacc[2 * pj], pla, vh[pj]);
                    mma16816(oacc[2 * pj + 1], pla, vh[pj] + 2);
                }
            }
        }
    }

    // ---- epilogue
    const float inv_lo = 1.0f / l_lo;
    const float inv_hi = 1.0f / l_hi;
    const int gr_lo = q0 + wq + (lane >> 2);
#pragma unroll
    for (int t = 0; t < 8; t++) {
        int c = cb + t * 8 + 2 * (lane & 3);
        {
            float o0 = oacc[t][0] * inv_lo, o1 = oacc[t][1] * inv_lo;
            uint32_t hh, ll;
            pconv(o0, o1, hh, ll);
            *(uint32_t*)(Oh + gr_lo * DMODEL + c) = hh;
            *(uint32_t*)(Ol + gr_lo * DMODEL + c) = ll;
        }
        {
            float o0 = oacc[t][2] * inv_hi, o1 = oacc[t][3] * inv_hi;
            uint32_t hh, ll;
            pconv(o0, o1, hh, ll);
            *(uint32_t*)(Oh + (gr_lo + 8) * DMODEL + c) = hh;
            *(uint32_t*)(Ol + (gr_lo + 8) * DMODEL + c) = ll;
        }
    }
}

// ---------------------------------------------------------------------------
extern "C" void kernel_launch(void* const* d_in, const int* in_sizes, int n_in,
                              void* d_out, int out_size)
{
    const float* Q  = (const float*)d_in[0];
    const float* K  = (const float*)d_in[1];
    const float* V  = (const float*)d_in[2];
    const float* WQ = (const float*)d_in[3];
    const float* WK = (const float*)d_in[4];
    const float* WV = (const float*)d_in[5];
    const float* WO = (const float*)d_in[6];
    float* out = (float*)d_out;

    __nv_bfloat16 *qih, *qil, *kih, *kil, *vih, *vil;
    __nv_bfloat16 *wqh, *wql, *wkh, *wkl, *wvh, *wvl, *woh, *wol;
    __nv_bfloat16 *qhh, *qhl, *khh, *khl, *vhh, *vhl, *ohh, *ohl;
    cudaGetSymbolAddress((void**)&qih, g_Qih); cudaGetSymbolAddress((void**)&qil, g_Qil);
    cudaGetSymbolAddress((void**)&kih, g_Kih); cudaGetSymbolAddress((void**)&kil, g_Kil);
    cudaGetSymbolAddress((void**)&vih, g_Vih); cudaGetSymbolAddress((void**)&vil, g_Vil);
    cudaGetSymbolAddress((void**)&wqh, g_Wqh); cudaGetSymbolAddress((void**)&wql, g_Wql);
    cudaGetSymbolAddress((void**)&wkh, g_Wkh); cudaGetSymbolAddress((void**)&wkl, g_Wkl);
    cudaGetSymbolAddress((void**)&wvh, g_Wvh); cudaGetSymbolAddress((void**)&wvl, g_Wvl);
    cudaGetSymbolAddress((void**)&woh, g_Woh); cudaGetSymbolAddress((void**)&wol, g_Wol);
    cudaGetSymbolAddress((void**)&qhh, g_Qhh); cudaGetSymbolAddress((void**)&qhl, g_Qhl);
    cudaGetSymbolAddress((void**)&khh, g_Khh); cudaGetSymbolAddress((void**)&khl, g_Khl);
    cudaGetSymbolAddress((void**)&vhh, g_Vhh); cudaGetSymbolAddress((void**)&vhl, g_Vhl);
    cudaGetSymbolAddress((void**)&ohh, g_Ohh); cudaGetSymbolAddress((void**)&ohl, g_Ohl);

    static bool attr_done = false;
    if (!attr_done) {
        cudaFuncSetAttribute(tc_gemm_kernel,
                             cudaFuncAttributeMaxDynamicSharedMemorySize, GSMEM);
        cudaFuncSetAttribute(flash_mma_kernel,
                             cudaFuncAttributeMaxDynamicSharedMemorySize, FSMEM);
        attr_done = true;
    }

    dim3 gg(DMODEL / 128, SEQL / 128);

    // [0] split inputs, [1] split weights
    split_inputs_kernel<<<dim3((SEQL * DMODEL / 4) / 256, 1, 3), 256>>>(
        Q, K, V, qih, qil, kih, kil, vih, vil);
    split_weights_kernel<<<dim3((DMODEL * DMODEL) / 256, 1, 4), 256>>>(
        WQ, WK, WV, WO, wqh, wql, wkh, wkl, wvh, wvl, woh, wol);

    // [2..4] projection GEMMs
    tc_gemm_kernel<<<gg, 256, GSMEM>>>(qih, qil, wqh, wql, nullptr, qhh, qhl);
    tc_gemm_kernel<<<gg, 256, GSMEM>>>(kih, kil, wkh, wkl, nullptr, khh, khl);
    tc_gemm_kernel<<<gg, 256, GSMEM>>>(vih, vil, wvh, wvl, nullptr, vhh, vhl);

    // [5] flash attention  (ncu -s 5 -c 1 profiles this launch)
    flash_mma_kernel<<<dim3(SEQL / 128, NH), 256, FSMEM>>>(
        qhh, qhl, khh, khl, vhh, vhl, ohh, ohl);

    // [6] output projection
    tc_gemm_kernel<<<gg, 256, GSMEM>>>(ohh, ohl, woh, wol, out, nullptr, nullptr);
}